// round 4
// baseline (speedup 1.0000x reference)
#include <cuda_runtime.h>
#include <cuda_fp16.h>
#include <cstdint>
#include <cstddef>

// ============================================================================
// AttentionNetwork: P=4096, LMAX=64, D=512, H=512  (fp16 mma.sync path)
// R4: re-tiled GEMM. 16 warps, warp tile 32x64, N-chunk 256, K-chunk 64.
// SMEM LDSM traffic halved vs R3 (3.15 MB/CTA), 4 warps/SMSP for latency.
// ============================================================================

#define NPATHS 4096

// ---------------- device scratch --------------------------------------------
__device__ __half g_W1T[512 * 512];   // pW1^T  [n][k]
__device__ __half g_aW1T[512 * 512];  // aW1^T  [n][k]
__device__ float g_pf[NPATHS * 512];  // paths_fea
__device__ float g_a[NPATHS];         // path logits
__device__ float g_aw[NPATHS];        // path softmax weights
__device__ float g_part[64 * 512];    // reduction partials

// ---------------- SMEM layout (bytes) ----------------------------------------
#define OFF_SC   0            // 128 floats
#define OFF_WTS  512          // 128 floats
#define OFF_B1   1024         // 512 floats
#define OFF_W2   3072         // 512 floats
#define OFF_XS   5120         // 128 rows x 1040B = 133120
#define OFF_WS   138240       // 2 bufs x 256 rows x 144B = 73728
#define WS_BUF   36864
#define XSTRIDE  1040
#define WSTRIDE  144
#define SMEM_BYTES 211968

// ---------------- PTX helpers ------------------------------------------------
__device__ __forceinline__ uint32_t smem_u32(const void* p) {
    uint32_t a;
    asm("{ .reg .u64 t; cvta.to.shared.u64 t, %1; cvt.u32.u64 %0, t; }"
        : "=r"(a) : "l"(p));
    return a;
}

__device__ __forceinline__ void ldsm4(uint32_t* r, uint32_t addr) {
    asm volatile("ldmatrix.sync.aligned.m8n8.x4.shared.b16 {%0,%1,%2,%3}, [%4];"
                 : "=r"(r[0]), "=r"(r[1]), "=r"(r[2]), "=r"(r[3]) : "r"(addr));
}

__device__ __forceinline__ void mma_f16(float* c, const uint32_t* a,
                                        uint32_t b0, uint32_t b1) {
    asm volatile(
        "mma.sync.aligned.m16n8k16.row.col.f32.f16.f16.f32 "
        "{%0,%1,%2,%3}, {%4,%5,%6,%7}, {%8,%9}, {%0,%1,%2,%3};"
        : "+f"(c[0]), "+f"(c[1]), "+f"(c[2]), "+f"(c[3])
        : "r"(a[0]), "r"(a[1]), "r"(a[2]), "r"(a[3]), "r"(b0), "r"(b1));
}

#define CP_ASYNC16(dst, src) \
    asm volatile("cp.async.cg.shared.global [%0], [%1], 16;" \
                 :: "r"(dst), "l"(src) : "memory")
#define CP_COMMIT() asm volatile("cp.async.commit_group;" ::: "memory")
#define CP_WAIT(n)  asm volatile("cp.async.wait_group %0;" :: "n"(n) : "memory")

// ---------------- shared device pieces ---------------------------------------

// 128 rows x 512 fp32 -> fp16 into Xs [row][stride 1040B]  (512 threads)
__device__ __forceinline__ void load_X_f16(const float* __restrict__ src,
                                           char* smem) {
    int tid = threadIdx.x;
#pragma unroll 4
    for (int i = 0; i < 32; i++) {
        int idx = tid + i * 512;          // 0..16383 float4 slots
        int m = idx >> 7;                 // 128 float4 per row
        int q = idx & 127;
        float4 v = *(const float4*)(src + (size_t)m * 512 + q * 4);
        __half2 p0, p1;
        p0.x = __float2half_rn(v.x); p0.y = __float2half_rn(v.y);
        p1.x = __float2half_rn(v.z); p1.y = __float2half_rn(v.w);
        uint2 st;
        st.x = *(uint32_t*)&p0;
        st.y = *(uint32_t*)&p1;
        *(uint2*)(smem + OFF_XS + m * XSTRIDE + q * 8) = st;
    }
}

// prefetch W sub-chunk s (= nc*8 + kc): 256 n-rows x 64 k -> Ws[buf]
__device__ __forceinline__ void prefetch_W(const __half* __restrict__ Wt,
                                           int s, int buf, uint32_t sb) {
    int tid = threadIdx.x;
    int nc = s >> 3, kc = s & 7;
    const __half* src = Wt + (size_t)(nc * 256) * 512 + kc * 64;
#pragma unroll
    for (int i = 0; i < 4; i++) {
        int idx = tid + i * 512;          // 0..2047 16B slots
        int nl = idx >> 3;                // 8 x 16B per row
        int q  = idx & 7;
        uint32_t dst = sb + OFF_WS + buf * WS_BUF + nl * WSTRIDE + q * 16;
        CP_ASYNC16(dst, src + (size_t)nl * 512 + q * 8);
    }
    CP_COMMIT();
}

// GEMM [128x512] @ W^T[512x512] folded to scores (512 threads).
// On exit sc[m] = sum_n relu(h[m][n]+b1[n])*w2[n].
__device__ __forceinline__ void gemm_scores(char* smem, uint32_t sb,
                                            const __half* __restrict__ Wt) {
    int tid = threadIdx.x;
    int lane = tid & 31, wid = tid >> 5;
    int m_part = wid & 3;                 // 32-row M slice
    int n_part = wid >> 2;                // 64-col slice within 256-N-chunk
    const float* b1s = (const float*)(smem + OFF_B1);
    const float* w2s = (const float*)(smem + OFF_W2);
    float* sc = (float*)(smem + OFF_SC);

    int lr = lane & 7;
    // A frag bases (two 16-row groups)
    uint32_t aA[2];
#pragma unroll
    for (int mi = 0; mi < 2; mi++)
        aA[mi] = sb + OFF_XS +
                 (m_part * 32 + mi * 16 + ((lane >> 3) & 1) * 8 + lr) * XSTRIDE +
                 (lane >> 4) * 16;
    // B frag bases (four 16-n groups within warp's 64 cols)
    uint32_t bA[4];
#pragma unroll
    for (int nj = 0; nj < 4; nj++)
        bA[nj] = sb + OFF_WS +
                 (n_part * 64 + nj * 16 + (lane >> 4) * 8 + lr) * WSTRIDE +
                 ((lane >> 3) & 1) * 16;

    float acc[2][8][4];
#pragma unroll
    for (int mi = 0; mi < 2; mi++)
#pragma unroll
        for (int nj = 0; nj < 8; nj++)
#pragma unroll
            for (int q = 0; q < 4; q++) acc[mi][nj][q] = 0.f;
    float rs[4] = {0.f, 0.f, 0.f, 0.f};

    prefetch_W(Wt, 0, 0, sb);

    for (int s = 0; s < 16; s++) {        // s = nc*8 + kc
        if (s + 1 < 16) prefetch_W(Wt, s + 1, (s + 1) & 1, sb);
        if (s + 1 < 16) { CP_WAIT(1); } else { CP_WAIT(0); }
        __syncthreads();

        int kc = s & 7;
        uint32_t buf = (s & 1) * WS_BUF;
#pragma unroll
        for (int k16 = 0; k16 < 4; k16++) {
            uint32_t koffX = kc * 128 + k16 * 32;   // bytes into X row
            uint32_t koffW = k16 * 32;              // bytes into W chunk row
            uint32_t A[2][4], B[4][4];
#pragma unroll
            for (int mi = 0; mi < 2; mi++) ldsm4(A[mi], aA[mi] + koffX);
#pragma unroll
            for (int nj = 0; nj < 4; nj++) ldsm4(B[nj], bA[nj] + buf + koffW);
#pragma unroll
            for (int mi = 0; mi < 2; mi++)
#pragma unroll
                for (int nj = 0; nj < 4; nj++) {
                    mma_f16(acc[mi][nj * 2],     A[mi], B[nj][0], B[nj][1]);
                    mma_f16(acc[mi][nj * 2 + 1], A[mi], B[nj][2], B[nj][3]);
                }
        }
        __syncthreads();   // buffer consumed, safe to overwrite

        if ((s & 7) == 7) {
            // fold this 256-wide N chunk into per-row score partials
            int nc = s >> 3;
            int t2 = (lane & 3) * 2;
#pragma unroll
            for (int mi = 0; mi < 2; mi++)
#pragma unroll
                for (int nj = 0; nj < 8; nj++) {
                    int n0 = nc * 256 + n_part * 64 + nj * 8 + t2;
                    float bb0 = b1s[n0], bb1 = b1s[n0 + 1];
                    float ww0 = w2s[n0], ww1 = w2s[n0 + 1];
                    float* cc = acc[mi][nj];
                    rs[mi * 2 + 0] += fmaxf(cc[0] + bb0, 0.f) * ww0 +
                                      fmaxf(cc[1] + bb1, 0.f) * ww1;
                    rs[mi * 2 + 1] += fmaxf(cc[2] + bb0, 0.f) * ww0 +
                                      fmaxf(cc[3] + bb1, 0.f) * ww1;
                    cc[0] = cc[1] = cc[2] = cc[3] = 0.f;
                }
        }
    }

    // reduce over the 4 lanes sharing a row, then atomically combine N-parts
#pragma unroll
    for (int i = 0; i < 4; i++) {
        rs[i] += __shfl_xor_sync(0xffffffffu, rs[i], 1);
        rs[i] += __shfl_xor_sync(0xffffffffu, rs[i], 2);
    }
    if ((lane & 3) == 0) {
        int g = lane >> 2;
        atomicAdd(&sc[m_part * 32 + g],      rs[0]);
        atomicAdd(&sc[m_part * 32 + g + 8],  rs[1]);
        atomicAdd(&sc[m_part * 32 + g + 16], rs[2]);
        atomicAdd(&sc[m_part * 32 + g + 24], rs[3]);
    }
    __syncthreads();
}

// ---------------- kernel 0: transpose + convert weights ----------------------
__global__ void k_conv(const float* __restrict__ src, __half* __restrict__ dst) {
    __shared__ float tile[64][65];
    int k0 = blockIdx.y * 64, n0 = blockIdx.x * 64;
    for (int i = threadIdx.x; i < 4096; i += 256) {
        int r = i >> 6, cth = i & 63;
        tile[r][cth] = src[(size_t)(k0 + r) * 512 + n0 + cth];
    }
    __syncthreads();
    for (int i = threadIdx.x; i < 4096; i += 256) {
        int r = i >> 6, cth = i & 63;
        dst[(size_t)(n0 + r) * 512 + k0 + cth] = __float2half_rn(tile[cth][r]);
    }
}

// ---------------- kernel 1: fused per-2-path stage ----------------------------
__global__ void __launch_bounds__(512, 1)
k_path(const float* __restrict__ nodes, const int* __restrict__ lengths,
       const float* __restrict__ pb1, const float* __restrict__ pw2,
       const float* __restrict__ pb2) {
    extern __shared__ char smem[];
    uint32_t sb = smem_u32(smem);
    int tid = threadIdx.x;

    float* b1s = (float*)(smem + OFF_B1);
    float* w2s = (float*)(smem + OFF_W2);
    float* sc  = (float*)(smem + OFF_SC);
    if (tid < 512) { b1s[tid] = pb1[tid]; w2s[tid] = pw2[tid]; }
    if (tid < 128) sc[tid] = 0.f;

    const float* X = nodes + (size_t)blockIdx.x * 128 * 512;
    load_X_f16(X, smem);
    __syncthreads();

    gemm_scores(smem, sb, g_W1T);

    // per-path masked softmax over 64 positions
    if (tid < 128) {
        int pl = tid >> 6, l = tid & 63;
        int len = lengths[blockIdx.x * 2 + pl];
        const float* ss = sc + pl * 64;
        float mx = -1e30f;
        for (int j = 0; j < 64; j++) if (j < len) mx = fmaxf(mx, ss[j]);
        float sum = 0.f;
        for (int j = 0; j < 64; j++) if (j < len) sum += expf(ss[j] - mx);
        float w = (l < len) ? expf(ss[l] - mx) / sum : 0.f;
        ((float*)(smem + OFF_WTS))[tid] = w;
    }
    __syncthreads();

    // weighted sum of X rows (fp16 in SMEM) -> paths_fea; one column pair/thread
    const float* wts = (const float*)(smem + OFF_WTS);
    {
        int pl = tid >> 8;                 // path within CTA
        int dp = tid & 255;                // fp16x2 column (0..255)
        float a0 = 0.f, a1 = 0.f;
        const char* base = smem + OFF_XS + dp * 4;
#pragma unroll 8
        for (int l = 0; l < 64; l++) {
            int m = pl * 64 + l;
            uint32_t v = *(const uint32_t*)(base + m * XSTRIDE);
            __half2 hv = *(__half2*)&v;
            float wl = wts[m];
            a0 = fmaf(wl, __half2float(hv.x), a0);
            a1 = fmaf(wl, __half2float(hv.y), a1);
        }
        float* dst = g_pf + ((size_t)blockIdx.x * 2 + pl) * 512 + dp * 2;
        dst[0] = a0;
        dst[1] = a1;
    }
}

// ---------------- kernel 2: path-level MLP logits -----------------------------
__global__ void __launch_bounds__(512, 1)
k_agg(const float* __restrict__ ab1, const float* __restrict__ aw2,
      const float* __restrict__ ab2) {
    extern __shared__ char smem[];
    uint32_t sb = smem_u32(smem);
    int tid = threadIdx.x;

    float* b1s = (float*)(smem + OFF_B1);
    float* w2s = (float*)(smem + OFF_W2);
    float* sc  = (float*)(smem + OFF_SC);
    if (tid < 512) { b1s[tid] = ab1[tid]; w2s[tid] = aw2[tid]; }
    if (tid < 128) sc[tid] = 0.f;

    const float* X = g_pf + (size_t)blockIdx.x * 128 * 512;
    load_X_f16(X, smem);
    __syncthreads();

    gemm_scores(smem, sb, g_aW1T);

    if (tid < 128) g_a[blockIdx.x * 128 + tid] = sc[tid] + ab2[0];
}

// ---------------- kernel 3: softmax over 4096 paths ---------------------------
__global__ void k_soft() {
    __shared__ float red[1024];
    int t = threadIdx.x;
    float m = -1e30f;
    for (int i = t; i < NPATHS; i += 1024) m = fmaxf(m, g_a[i]);
    red[t] = m;
    __syncthreads();
    for (int s = 512; s > 0; s >>= 1) {
        if (t < s) red[t] = fmaxf(red[t], red[t + s]);
        __syncthreads();
    }
    float M = red[0];
    __syncthreads();
    float sum = 0.f;
    for (int i = t; i < NPATHS; i += 1024) sum += expf(g_a[i] - M);
    red[t] = sum;
    __syncthreads();
    for (int s = 512; s > 0; s >>= 1) {
        if (t < s) red[t] += red[t + s];
        __syncthreads();
    }
    float S = red[0];
    for (int i = t; i < NPATHS; i += 1024) g_aw[i] = expf(g_a[i] - M) / S;
}

// ---------------- kernel 4: partial weighted sums -----------------------------
__global__ void k_red() {
    int b = blockIdx.x, t = threadIdx.x;
    float a0 = 0.f, a1 = 0.f;
    for (int p = 0; p < 64; p++) {
        int pg = b * 64 + p;
        float w = g_aw[pg];
        const float* row = g_pf + (size_t)pg * 512;
        a0 = fmaf(w, row[t], a0);
        a1 = fmaf(w, row[t + 256], a1);
    }
    g_part[(size_t)b * 512 + t] = a0;
    g_part[(size_t)b * 512 + t + 256] = a1;
}

// ---------------- kernel 5: final reduction -----------------------------------
__global__ void k_fin(float* __restrict__ out) {
    int t = threadIdx.x;
    float s = 0.f;
    for (int b = 0; b < 64; b++) s += g_part[(size_t)b * 512 + t];
    out[t] = s;
}

// ---------------- entry -------------------------------------------------------
extern "C" void kernel_launch(void* const* d_in, const int* in_sizes, int n_in,
                              void* d_out, int out_size) {
    const float* nodes   = (const float*)d_in[0];
    const int*   lengths = (const int*)  d_in[1];
    const float* pW1     = (const float*)d_in[2];
    const float* pb1     = (const float*)d_in[3];
    const float* pw2     = (const float*)d_in[4];
    const float* pb2     = (const float*)d_in[5];
    const float* aW1     = (const float*)d_in[6];
    const float* ab1     = (const float*)d_in[7];
    const float* aw2     = (const float*)d_in[8];
    const float* ab2     = (const float*)d_in[9];
    float* out = (float*)d_out;

    cudaFuncSetAttribute(k_path, cudaFuncAttributeMaxDynamicSharedMemorySize, SMEM_BYTES);
    cudaFuncSetAttribute(k_agg,  cudaFuncAttributeMaxDynamicSharedMemorySize, SMEM_BYTES);

    __half* w1t;  cudaGetSymbolAddress((void**)&w1t,  g_W1T);
    __half* aw1t; cudaGetSymbolAddress((void**)&aw1t, g_aW1T);

    k_conv<<<dim3(8, 8), 256>>>(pW1, w1t);     // launch 0
    k_conv<<<dim3(8, 8), 256>>>(aW1, aw1t);    // launch 1
    k_path<<<NPATHS / 2, 512, SMEM_BYTES>>>(nodes, lengths, pb1, pw2, pb2);  // 2
    k_agg<<<NPATHS / 128, 512, SMEM_BYTES>>>(ab1, aw2, ab2);                 // 3
    k_soft<<<1, 1024>>>();
    k_red<<<64, 256>>>();
    k_fin<<<1, 512>>>(out);
}

// round 5
// speedup vs baseline: 1.2881x; 1.2881x over previous
#include <cuda_runtime.h>
#include <cuda_fp16.h>
#include <cstdint>
#include <cstddef>

// ============================================================================
// AttentionNetwork: P=4096, LMAX=64, D=512, H=512  (fp16 mma.sync path)
// R5: 256 threads (reg cap 255 -> no spills), warp tile 64x32,
// N-chunk 128, K-chunk 64, 32 pipelined W sub-chunks. 96 B LDSM per MMA.
// ============================================================================

#define NPATHS 4096

// ---------------- device scratch --------------------------------------------
__device__ __half g_W1T[512 * 512];   // pW1^T  [n][k]
__device__ __half g_aW1T[512 * 512];  // aW1^T  [n][k]
__device__ float g_pf[NPATHS * 512];  // paths_fea
__device__ float g_a[NPATHS];         // path logits
__device__ float g_aw[NPATHS];        // path softmax weights
__device__ float g_part[64 * 512];    // reduction partials

// ---------------- SMEM layout (bytes) ----------------------------------------
#define OFF_SC   0            // 128 floats
#define OFF_WTS  512          // 128 floats
#define OFF_B1   1024         // 512 floats
#define OFF_W2   3072         // 512 floats
#define OFF_XS   5120         // 128 rows x 1040B = 133120
#define OFF_WS   138240       // 2 bufs x 128 rows x 144B = 36864
#define WS_BUF   18432
#define XSTRIDE  1040
#define WSTRIDE  144
#define SMEM_BYTES 175104

// ---------------- PTX helpers ------------------------------------------------
__device__ __forceinline__ uint32_t smem_u32(const void* p) {
    uint32_t a;
    asm("{ .reg .u64 t; cvta.to.shared.u64 t, %1; cvt.u32.u64 %0, t; }"
        : "=r"(a) : "l"(p));
    return a;
}

__device__ __forceinline__ void ldsm4(uint32_t* r, uint32_t addr) {
    asm volatile("ldmatrix.sync.aligned.m8n8.x4.shared.b16 {%0,%1,%2,%3}, [%4];"
                 : "=r"(r[0]), "=r"(r[1]), "=r"(r[2]), "=r"(r[3]) : "r"(addr));
}

__device__ __forceinline__ void mma_f16(float* c, const uint32_t* a,
                                        uint32_t b0, uint32_t b1) {
    asm volatile(
        "mma.sync.aligned.m16n8k16.row.col.f32.f16.f16.f32 "
        "{%0,%1,%2,%3}, {%4,%5,%6,%7}, {%8,%9}, {%0,%1,%2,%3};"
        : "+f"(c[0]), "+f"(c[1]), "+f"(c[2]), "+f"(c[3])
        : "r"(a[0]), "r"(a[1]), "r"(a[2]), "r"(a[3]), "r"(b0), "r"(b1));
}

#define CP_ASYNC16(dst, src) \
    asm volatile("cp.async.cg.shared.global [%0], [%1], 16;" \
                 :: "r"(dst), "l"(src) : "memory")
#define CP_COMMIT() asm volatile("cp.async.commit_group;" ::: "memory")
#define CP_WAIT(n)  asm volatile("cp.async.wait_group %0;" :: "n"(n) : "memory")

// ---------------- shared device pieces ---------------------------------------

// 128 rows x 512 fp32 -> fp16 into Xs [row][stride 1040B]  (256 threads)
__device__ __forceinline__ void load_X_f16(const float* __restrict__ src,
                                           char* smem) {
    int tid = threadIdx.x;
#pragma unroll 4
    for (int i = 0; i < 64; i++) {
        int idx = tid + i * 256;          // 0..16383 float4 slots
        int m = idx >> 7;                 // 128 float4 per row
        int q = idx & 127;
        float4 v = *(const float4*)(src + (size_t)m * 512 + q * 4);
        __half2 p0, p1;
        p0.x = __float2half_rn(v.x); p0.y = __float2half_rn(v.y);
        p1.x = __float2half_rn(v.z); p1.y = __float2half_rn(v.w);
        uint2 st;
        st.x = *(uint32_t*)&p0;
        st.y = *(uint32_t*)&p1;
        *(uint2*)(smem + OFF_XS + m * XSTRIDE + q * 8) = st;
    }
}

// prefetch W sub-chunk s (= nc*8 + kc): 128 n-rows x 64 k -> Ws[buf]
__device__ __forceinline__ void prefetch_W(const __half* __restrict__ Wt,
                                           int s, int buf, uint32_t sb) {
    int tid = threadIdx.x;
    int nc = s >> 3, kc = s & 7;
    const __half* src = Wt + (size_t)(nc * 128) * 512 + kc * 64;
#pragma unroll
    for (int i = 0; i < 4; i++) {
        int idx = tid + i * 256;          // 0..1023 16B slots
        int nl = idx >> 3;                // 8 x 16B per row
        int q  = idx & 7;
        uint32_t dst = sb + OFF_WS + buf * WS_BUF + nl * WSTRIDE + q * 16;
        CP_ASYNC16(dst, src + (size_t)nl * 512 + q * 8);
    }
    CP_COMMIT();
}

// GEMM [128x512] @ W^T[512x512] folded to scores (256 threads, 8 warps).
// Warp tile 64x32. On exit sc[m] = sum_n relu(h[m][n]+b1[n])*w2[n].
__device__ __forceinline__ void gemm_scores(char* smem, uint32_t sb,
                                            const __half* __restrict__ Wt) {
    int tid = threadIdx.x;
    int lane = tid & 31, wid = tid >> 5;
    int m_part = wid & 1;                 // 64-row M slice
    int n_part = wid >> 1;                // 32-col slice within 128-N-chunk
    const float* b1s = (const float*)(smem + OFF_B1);
    const float* w2s = (const float*)(smem + OFF_W2);
    float* sc = (float*)(smem + OFF_SC);

    int lr = lane & 7;
    // A frag bases: four 16-row groups of the warp's 64 rows
    uint32_t aA[4];
#pragma unroll
    for (int mi = 0; mi < 4; mi++)
        aA[mi] = sb + OFF_XS +
                 (m_part * 64 + mi * 16 + ((lane >> 3) & 1) * 8 + lr) * XSTRIDE +
                 (lane >> 4) * 16;
    // B frag bases: two 16-n groups of the warp's 32 cols
    uint32_t bA[2];
#pragma unroll
    for (int nj = 0; nj < 2; nj++)
        bA[nj] = sb + OFF_WS +
                 (n_part * 32 + nj * 16 + (lane >> 4) * 8 + lr) * WSTRIDE +
                 ((lane >> 3) & 1) * 16;

    float acc[4][4][4];                   // [mi][n8 group][quad]
#pragma unroll
    for (int mi = 0; mi < 4; mi++)
#pragma unroll
        for (int nq = 0; nq < 4; nq++)
#pragma unroll
            for (int q = 0; q < 4; q++) acc[mi][nq][q] = 0.f;
    float rs[8];
#pragma unroll
    for (int i = 0; i < 8; i++) rs[i] = 0.f;

    prefetch_W(Wt, 0, 0, sb);

    for (int s = 0; s < 32; s++) {        // s = nc*8 + kc
        if (s + 1 < 32) prefetch_W(Wt, s + 1, (s + 1) & 1, sb);
        if (s + 1 < 32) { CP_WAIT(1); } else { CP_WAIT(0); }
        __syncthreads();

        int kc = s & 7;
        uint32_t buf = (s & 1) * WS_BUF;
#pragma unroll
        for (int k16 = 0; k16 < 4; k16++) {
            uint32_t koffX = kc * 128 + k16 * 32;   // bytes into X row
            uint32_t koffW = k16 * 32;              // bytes into W chunk row
            uint32_t A[4][4], B[2][4];
#pragma unroll
            for (int mi = 0; mi < 4; mi++) ldsm4(A[mi], aA[mi] + koffX);
#pragma unroll
            for (int nj = 0; nj < 2; nj++) ldsm4(B[nj], bA[nj] + buf + koffW);
#pragma unroll
            for (int mi = 0; mi < 4; mi++)
#pragma unroll
                for (int nj = 0; nj < 2; nj++) {
                    mma_f16(acc[mi][nj * 2],     A[mi], B[nj][0], B[nj][1]);
                    mma_f16(acc[mi][nj * 2 + 1], A[mi], B[nj][2], B[nj][3]);
                }
        }
        __syncthreads();   // buffer consumed, safe to overwrite

        if ((s & 7) == 7) {
            // fold this 128-wide N chunk into per-row score partials
            int nc = s >> 3;
            int t2 = (lane & 3) * 2;
#pragma unroll
            for (int mi = 0; mi < 4; mi++)
#pragma unroll
                for (int nq = 0; nq < 4; nq++) {
                    int n0 = nc * 128 + n_part * 32 + nq * 8 + t2;
                    float bb0 = b1s[n0], bb1 = b1s[n0 + 1];
                    float ww0 = w2s[n0], ww1 = w2s[n0 + 1];
                    float* cc = acc[mi][nq];
                    rs[mi * 2 + 0] += fmaxf(cc[0] + bb0, 0.f) * ww0 +
                                      fmaxf(cc[1] + bb1, 0.f) * ww1;
                    rs[mi * 2 + 1] += fmaxf(cc[2] + bb0, 0.f) * ww0 +
                                      fmaxf(cc[3] + bb1, 0.f) * ww1;
                    cc[0] = cc[1] = cc[2] = cc[3] = 0.f;
                }
        }
    }

    // reduce over the 4 lanes sharing each row, then combine N-parts
#pragma unroll
    for (int i = 0; i < 8; i++) {
        rs[i] += __shfl_xor_sync(0xffffffffu, rs[i], 1);
        rs[i] += __shfl_xor_sync(0xffffffffu, rs[i], 2);
    }
    if ((lane & 3) == 0) {
        int g = lane >> 2;                // row group 0..7
#pragma unroll
        for (int mi = 0; mi < 4; mi++) {
            atomicAdd(&sc[m_part * 64 + mi * 16 + g],     rs[mi * 2 + 0]);
            atomicAdd(&sc[m_part * 64 + mi * 16 + 8 + g], rs[mi * 2 + 1]);
        }
    }
    __syncthreads();
}

// ---------------- kernel 0: transpose + convert weights ----------------------
__global__ void k_conv(const float* __restrict__ src, __half* __restrict__ dst) {
    __shared__ float tile[64][65];
    int k0 = blockIdx.y * 64, n0 = blockIdx.x * 64;
    for (int i = threadIdx.x; i < 4096; i += 256) {
        int r = i >> 6, cth = i & 63;
        tile[r][cth] = src[(size_t)(k0 + r) * 512 + n0 + cth];
    }
    __syncthreads();
    for (int i = threadIdx.x; i < 4096; i += 256) {
        int r = i >> 6, cth = i & 63;
        dst[(size_t)(n0 + r) * 512 + k0 + cth] = __float2half_rn(tile[cth][r]);
    }
}

// ---------------- kernel 1: fused per-2-path stage ----------------------------
__global__ void __launch_bounds__(256, 1)
k_path(const float* __restrict__ nodes, const int* __restrict__ lengths,
       const float* __restrict__ pb1, const float* __restrict__ pw2,
       const float* __restrict__ pb2) {
    extern __shared__ char smem[];
    uint32_t sb = smem_u32(smem);
    int tid = threadIdx.x;

    float* b1s = (float*)(smem + OFF_B1);
    float* w2s = (float*)(smem + OFF_W2);
    float* sc  = (float*)(smem + OFF_SC);
    for (int i = tid; i < 512; i += 256) { b1s[i] = pb1[i]; w2s[i] = pw2[i]; }
    if (tid < 128) sc[tid] = 0.f;

    const float* X = nodes + (size_t)blockIdx.x * 128 * 512;
    load_X_f16(X, smem);
    __syncthreads();

    gemm_scores(smem, sb, g_W1T);

    // per-path masked softmax over 64 positions
    if (tid < 128) {
        int pl = tid >> 6, l = tid & 63;
        int len = lengths[blockIdx.x * 2 + pl];
        const float* ss = sc + pl * 64;
        float mx = -1e30f;
        for (int j = 0; j < 64; j++) if (j < len) mx = fmaxf(mx, ss[j]);
        float sum = 0.f;
        for (int j = 0; j < 64; j++) if (j < len) sum += expf(ss[j] - mx);
        float w = (l < len) ? expf(ss[l] - mx) / sum : 0.f;
        ((float*)(smem + OFF_WTS))[tid] = w;
    }
    __syncthreads();

    // weighted sum of X rows (fp16 in SMEM) -> paths_fea
    const float* wts = (const float*)(smem + OFF_WTS);
#pragma unroll
    for (int it = 0; it < 2; it++) {
        int pl = tid >> 7;
        int dp = (tid & 127) + it * 128;       // fp16x2 column (0..255)
        float a0 = 0.f, a1 = 0.f;
        const char* base = smem + OFF_XS + dp * 4;
#pragma unroll 8
        for (int l = 0; l < 64; l++) {
            int m = pl * 64 + l;
            uint32_t v = *(const uint32_t*)(base + m * XSTRIDE);
            __half2 hv = *(__half2*)&v;
            float wl = wts[m];
            a0 = fmaf(wl, __half2float(hv.x), a0);
            a1 = fmaf(wl, __half2float(hv.y), a1);
        }
        float* dst = g_pf + ((size_t)blockIdx.x * 2 + pl) * 512 + dp * 2;
        dst[0] = a0;
        dst[1] = a1;
    }
}

// ---------------- kernel 2: path-level MLP logits -----------------------------
__global__ void __launch_bounds__(256, 1)
k_agg(const float* __restrict__ ab1, const float* __restrict__ aw2,
      const float* __restrict__ ab2) {
    extern __shared__ char smem[];
    uint32_t sb = smem_u32(smem);
    int tid = threadIdx.x;

    float* b1s = (float*)(smem + OFF_B1);
    float* w2s = (float*)(smem + OFF_W2);
    float* sc  = (float*)(smem + OFF_SC);
    for (int i = tid; i < 512; i += 256) { b1s[i] = ab1[i]; w2s[i] = aw2[i]; }
    if (tid < 128) sc[tid] = 0.f;

    const float* X = g_pf + (size_t)blockIdx.x * 128 * 512;
    load_X_f16(X, smem);
    __syncthreads();

    gemm_scores(smem, sb, g_aW1T);

    if (tid < 128) g_a[blockIdx.x * 128 + tid] = sc[tid] + ab2[0];
}

// ---------------- kernel 3: softmax over 4096 paths ---------------------------
__global__ void k_soft() {
    __shared__ float red[1024];
    int t = threadIdx.x;
    float m = -1e30f;
    for (int i = t; i < NPATHS; i += 1024) m = fmaxf(m, g_a[i]);
    red[t] = m;
    __syncthreads();
    for (int s = 512; s > 0; s >>= 1) {
        if (t < s) red[t] = fmaxf(red[t], red[t + s]);
        __syncthreads();
    }
    float M = red[0];
    __syncthreads();
    float sum = 0.f;
    for (int i = t; i < NPATHS; i += 1024) sum += expf(g_a[i] - M);
    red[t] = sum;
    __syncthreads();
    for (int s = 512; s > 0; s >>= 1) {
        if (t < s) red[t] += red[t + s];
        __syncthreads();
    }
    float S = red[0];
    for (int i = t; i < NPATHS; i += 1024) g_aw[i] = expf(g_a[i] - M) / S;
}

// ---------------- kernel 4: partial weighted sums -----------------------------
__global__ void k_red() {
    int b = blockIdx.x, t = threadIdx.x;
    float a0 = 0.f, a1 = 0.f;
    for (int p = 0; p < 64; p++) {
        int pg = b * 64 + p;
        float w = g_aw[pg];
        const float* row = g_pf + (size_t)pg * 512;
        a0 = fmaf(w, row[t], a0);
        a1 = fmaf(w, row[t + 256], a1);
    }
    g_part[(size_t)b * 512 + t] = a0;
    g_part[(size_t)b * 512 + t + 256] = a1;
}

// ---------------- kernel 5: final reduction -----------------------------------
__global__ void k_fin(float* __restrict__ out) {
    int t = threadIdx.x;
    float s = 0.f;
    for (int b = 0; b < 64; b++) s += g_part[(size_t)b * 512 + t];
    out[t] = s;
}

// ---------------- entry -------------------------------------------------------
extern "C" void kernel_launch(void* const* d_in, const int* in_sizes, int n_in,
                              void* d_out, int out_size) {
    const float* nodes   = (const float*)d_in[0];
    const int*   lengths = (const int*)  d_in[1];
    const float* pW1     = (const float*)d_in[2];
    const float* pb1     = (const float*)d_in[3];
    const float* pw2     = (const float*)d_in[4];
    const float* pb2     = (const float*)d_in[5];
    const float* aW1     = (const float*)d_in[6];
    const float* ab1     = (const float*)d_in[7];
    const float* aw2     = (const float*)d_in[8];
    const float* ab2     = (const float*)d_in[9];
    float* out = (float*)d_out;

    cudaFuncSetAttribute(k_path, cudaFuncAttributeMaxDynamicSharedMemorySize, SMEM_BYTES);
    cudaFuncSetAttribute(k_agg,  cudaFuncAttributeMaxDynamicSharedMemorySize, SMEM_BYTES);

    __half* w1t;  cudaGetSymbolAddress((void**)&w1t,  g_W1T);
    __half* aw1t; cudaGetSymbolAddress((void**)&aw1t, g_aW1T);

    k_conv<<<dim3(8, 8), 256>>>(pW1, w1t);     // launch 0
    k_conv<<<dim3(8, 8), 256>>>(aW1, aw1t);    // launch 1
    k_path<<<NPATHS / 2, 256, SMEM_BYTES>>>(nodes, lengths, pb1, pw2, pb2);  // 2
    k_agg<<<NPATHS / 128, 256, SMEM_BYTES>>>(ab1, aw2, ab2);                 // 3
    k_soft<<<1, 1024>>>();
    k_red<<<64, 256>>>();
    k_fin<<<1, 512>>>(out);
}

// round 6
// speedup vs baseline: 1.3254x; 1.0290x over previous
#include <cuda_runtime.h>
#include <cuda_fp16.h>
#include <cstdint>
#include <cstddef>

// ============================================================================
// AttentionNetwork: P=4096, LMAX=64, D=512, H=512  (fp16 mma.sync path)
// R6: register-pipelined fragments (LDSM k16+1 issued before MMAs of k16),
// 4-deep cp.async W pipeline (CP_WAIT(3)), W prefetch overlapped with X load,
// k_agg re-tiled to M=64/grid=64 (1 full wave). Templated GEMM.
// ============================================================================

#define NPATHS 4096

// ---------------- device scratch --------------------------------------------
__device__ __half g_W1T[512 * 512];   // pW1^T  [n][k]
__device__ __half g_aW1T[512 * 512];  // aW1^T  [n][k]
__device__ float g_pf[NPATHS * 512];  // paths_fea
__device__ float g_a[NPATHS];         // path logits
__device__ float g_aw[NPATHS];        // path softmax weights
__device__ float g_part[64 * 512];    // reduction partials

// ---------------- SMEM layout (bytes) ----------------------------------------
#define OFF_SC   0            // 128 floats
#define OFF_WTS  512          // 128 floats
#define OFF_B1   1024         // 512 floats
#define OFF_W2   3072         // 512 floats
#define OFF_XS   5120         // X tile: ROWS x 1040B
#define XSTRIDE  1040
#define WSTRIDE  144

// k_path: 128 X rows, NP=4 (W chunk 128x64, buf 18432)
#define OFFWS_PATH  138240                    // 5120 + 128*1040
#define SMEM_PATH   (138240 + 4 * 18432)      // 211968
// k_agg: 64 X rows, NP=8 (W chunk 256x64, buf 36864)
#define OFFWS_AGG   71680                     // 5120 + 64*1040
#define SMEM_AGG    (71680 + 4 * 36864)       // 219136

// ---------------- PTX helpers ------------------------------------------------
__device__ __forceinline__ uint32_t smem_u32(const void* p) {
    uint32_t a;
    asm("{ .reg .u64 t; cvta.to.shared.u64 t, %1; cvt.u32.u64 %0, t; }"
        : "=r"(a) : "l"(p));
    return a;
}

__device__ __forceinline__ void ldsm4(uint32_t* r, uint32_t addr) {
    asm volatile("ldmatrix.sync.aligned.m8n8.x4.shared.b16 {%0,%1,%2,%3}, [%4];"
                 : "=r"(r[0]), "=r"(r[1]), "=r"(r[2]), "=r"(r[3]) : "r"(addr));
}

__device__ __forceinline__ void mma_f16(float* c, const uint32_t* a,
                                        uint32_t b0, uint32_t b1) {
    asm volatile(
        "mma.sync.aligned.m16n8k16.row.col.f32.f16.f16.f32 "
        "{%0,%1,%2,%3}, {%4,%5,%6,%7}, {%8,%9}, {%0,%1,%2,%3};"
        : "+f"(c[0]), "+f"(c[1]), "+f"(c[2]), "+f"(c[3])
        : "r"(a[0]), "r"(a[1]), "r"(a[2]), "r"(a[3]), "r"(b0), "r"(b1));
}

#define CP_ASYNC16(dst, src) \
    asm volatile("cp.async.cg.shared.global [%0], [%1], 16;" \
                 :: "r"(dst), "l"(src) : "memory")
#define CP_COMMIT() asm volatile("cp.async.commit_group;" ::: "memory")
#define CP_WAIT(n)  asm volatile("cp.async.wait_group %0;" :: "n"(n) : "memory")

// ---------------- shared device pieces ---------------------------------------

// ROWS x 512 fp32 -> fp16 into Xs [row][stride 1040B]  (256 threads)
template <int ROWS>
__device__ __forceinline__ void load_X_f16(const float* __restrict__ src,
                                           char* smem) {
    int tid = threadIdx.x;
#pragma unroll 4
    for (int i = 0; i < ROWS / 2; i++) {
        int idx = tid + i * 256;          // float4 slots
        int m = idx >> 7;                 // 128 float4 per row
        int q = idx & 127;
        float4 v = *(const float4*)(src + (size_t)m * 512 + q * 4);
        __half2 p0, p1;
        p0.x = __float2half_rn(v.x); p0.y = __float2half_rn(v.y);
        p1.x = __float2half_rn(v.z); p1.y = __float2half_rn(v.w);
        uint2 st;
        st.x = *(uint32_t*)&p0;
        st.y = *(uint32_t*)&p1;
        *(uint2*)(smem + OFF_XS + m * XSTRIDE + q * 8) = st;
    }
}

// prefetch W sub-chunk s (= nc*8 + kc): NP*32 n-rows x 64 k -> Ws[buf]
template <int NP, int OFFWS>
__device__ __forceinline__ void prefetch_W(const __half* __restrict__ Wt,
                                           int s, int buf, uint32_t sb) {
    constexpr int WSBUF = NP * 32 * WSTRIDE;
    int tid = threadIdx.x;
    int nc = s >> 3, kc = s & 7;
    const __half* src = Wt + (size_t)(nc * NP * 32) * 512 + kc * 64;
#pragma unroll
    for (int i = 0; i < NP; i++) {
        int idx = tid + i * 256;          // 16B slots
        int nl = idx >> 3;                // 8 x 16B per row
        int q  = idx & 7;
        uint32_t dst = sb + OFFWS + buf * WSBUF + nl * WSTRIDE + q * 16;
        CP_ASYNC16(dst, src + (size_t)nl * 512 + q * 8);
    }
    CP_COMMIT();
}

template <int NP, int OFFWS>
__device__ __forceinline__ void gemm_preamble(const __half* __restrict__ Wt,
                                              uint32_t sb) {
    prefetch_W<NP, OFFWS>(Wt, 0, 0, sb);
    prefetch_W<NP, OFFWS>(Wt, 1, 1, sb);
    prefetch_W<NP, OFFWS>(Wt, 2, 2, sb);
}

// GEMM [MP*64 x 512] @ W^T[512x512] folded to scores. 256 threads, 8 warps,
// warp tile 64x32. On exit sc[m] = sum_n relu(h[m][n]+b1[n])*w2[n].
// Requires: gemm_preamble already called, X tile + b1/w2 + sc zero in SMEM.
template <int MP, int NP, int OFFWS>
__device__ __forceinline__ void gemm_mainloop(char* smem, uint32_t sb,
                                              const __half* __restrict__ Wt) {
    constexpr int WSBUF = NP * 32 * WSTRIDE;
    constexpr int S = (512 / (NP * 32)) * 8;   // total sub-chunks
    int tid = threadIdx.x;
    int lane = tid & 31, wid = tid >> 5;
    int m_part = (MP == 1) ? 0 : (wid & (MP - 1));
    int n_part = wid / MP;
    const float* b1s = (const float*)(smem + OFF_B1);
    const float* w2s = (const float*)(smem + OFF_W2);
    float* sc = (float*)(smem + OFF_SC);

    int lr = lane & 7;
    uint32_t aA[4];
#pragma unroll
    for (int mi = 0; mi < 4; mi++)
        aA[mi] = sb + OFF_XS +
                 (m_part * 64 + mi * 16 + ((lane >> 3) & 1) * 8 + lr) * XSTRIDE +
                 (lane >> 4) * 16;
    uint32_t bA[2];
#pragma unroll
    for (int nj = 0; nj < 2; nj++)
        bA[nj] = sb + OFFWS +
                 (n_part * 32 + nj * 16 + (lane >> 4) * 8 + lr) * WSTRIDE +
                 ((lane >> 3) & 1) * 16;

    float acc[4][4][4];
#pragma unroll
    for (int mi = 0; mi < 4; mi++)
#pragma unroll
        for (int nq = 0; nq < 4; nq++)
#pragma unroll
            for (int q = 0; q < 4; q++) acc[mi][nq][q] = 0.f;
    float rs[8];
#pragma unroll
    for (int i = 0; i < 8; i++) rs[i] = 0.f;

    for (int s = 0; s < S; s++) {
        __syncthreads();                      // prev reads of buf[(s+3)&3] done
        if (s + 3 < S) prefetch_W<NP, OFFWS>(Wt, s + 3, (s + 3) & 3, sb);
        else CP_COMMIT();                     // keep group count aligned
        CP_WAIT(3);                           // chunk s complete (thread-local)
        __syncthreads();                      // chunk s visible to all

        int kc = s & 7;
        uint32_t buf = (uint32_t)(s & 3) * WSBUF;
        uint32_t A[2][4][4], B[2][2][4];
        // preload k16 = 0 fragments
        {
            uint32_t kx = kc * 128;
#pragma unroll
            for (int mi = 0; mi < 4; mi++) ldsm4(A[0][mi], aA[mi] + kx);
#pragma unroll
            for (int nj = 0; nj < 2; nj++) ldsm4(B[0][nj], bA[nj] + buf);
        }
#pragma unroll
        for (int k16 = 0; k16 < 4; k16++) {
            int cur = k16 & 1, nxt = cur ^ 1;
            if (k16 < 3) {                    // prefetch next frags first
                uint32_t kxX = kc * 128 + (k16 + 1) * 32;
                uint32_t kxW = (k16 + 1) * 32;
#pragma unroll
                for (int mi = 0; mi < 4; mi++) ldsm4(A[nxt][mi], aA[mi] + kxX);
#pragma unroll
                for (int nj = 0; nj < 2; nj++) ldsm4(B[nxt][nj], bA[nj] + buf + kxW);
            }
#pragma unroll
            for (int mi = 0; mi < 4; mi++)
#pragma unroll
                for (int nj = 0; nj < 2; nj++) {
                    mma_f16(acc[mi][nj * 2],     A[cur][mi], B[cur][nj][0], B[cur][nj][1]);
                    mma_f16(acc[mi][nj * 2 + 1], A[cur][mi], B[cur][nj][2], B[cur][nj][3]);
                }
        }

        if ((s & 7) == 7) {
            // fold this N chunk into per-row score partials
            int nc = s >> 3;
            int t2 = (lane & 3) * 2;
#pragma unroll
            for (int mi = 0; mi < 4; mi++)
#pragma unroll
                for (int nq = 0; nq < 4; nq++) {
                    int n0 = nc * (NP * 32) + n_part * 32 + nq * 8 + t2;
                    float bb0 = b1s[n0], bb1 = b1s[n0 + 1];
                    float ww0 = w2s[n0], ww1 = w2s[n0 + 1];
                    float* cc = acc[mi][nq];
                    rs[mi * 2 + 0] += fmaxf(cc[0] + bb0, 0.f) * ww0 +
                                      fmaxf(cc[1] + bb1, 0.f) * ww1;
                    rs[mi * 2 + 1] += fmaxf(cc[2] + bb0, 0.f) * ww0 +
                                      fmaxf(cc[3] + bb1, 0.f) * ww1;
                    cc[0] = cc[1] = cc[2] = cc[3] = 0.f;
                }
        }
    }

    // reduce over the 4 lanes sharing each row, then combine N-parts
#pragma unroll
    for (int i = 0; i < 8; i++) {
        rs[i] += __shfl_xor_sync(0xffffffffu, rs[i], 1);
        rs[i] += __shfl_xor_sync(0xffffffffu, rs[i], 2);
    }
    if ((lane & 3) == 0) {
        int g = lane >> 2;                // row group 0..7
#pragma unroll
        for (int mi = 0; mi < 4; mi++) {
            atomicAdd(&sc[m_part * 64 + mi * 16 + g],     rs[mi * 2 + 0]);
            atomicAdd(&sc[m_part * 64 + mi * 16 + 8 + g], rs[mi * 2 + 1]);
        }
    }
    __syncthreads();
}

// ---------------- kernel 0: transpose + convert weights ----------------------
__global__ void k_conv(const float* __restrict__ src, __half* __restrict__ dst) {
    __shared__ float tile[64][65];
    int k0 = blockIdx.y * 64, n0 = blockIdx.x * 64;
    for (int i = threadIdx.x; i < 4096; i += 256) {
        int r = i >> 6, cth = i & 63;
        tile[r][cth] = src[(size_t)(k0 + r) * 512 + n0 + cth];
    }
    __syncthreads();
    for (int i = threadIdx.x; i < 4096; i += 256) {
        int r = i >> 6, cth = i & 63;
        dst[(size_t)(n0 + r) * 512 + k0 + cth] = __float2half_rn(tile[cth][r]);
    }
}

// ---------------- kernel 1: fused per-2-path stage ----------------------------
__global__ void __launch_bounds__(256, 1)
k_path(const float* __restrict__ nodes, const int* __restrict__ lengths,
       const float* __restrict__ pb1, const float* __restrict__ pw2,
       const float* __restrict__ pb2) {
    extern __shared__ char smem[];
    uint32_t sb = smem_u32(smem);
    int tid = threadIdx.x;

    gemm_preamble<4, OFFWS_PATH>(g_W1T, sb);   // W chunks stream during X load

    float* b1s = (float*)(smem + OFF_B1);
    float* w2s = (float*)(smem + OFF_W2);
    float* sc  = (float*)(smem + OFF_SC);
    for (int i = tid; i < 512; i += 256) { b1s[i] = pb1[i]; w2s[i] = pw2[i]; }
    if (tid < 128) sc[tid] = 0.f;

    const float* X = nodes + (size_t)blockIdx.x * 128 * 512;
    load_X_f16<128>(X, smem);
    // first __syncthreads inside mainloop publishes X + sc + b1/w2

    gemm_mainloop<2, 4, OFFWS_PATH>(smem, sb, g_W1T);

    // per-path masked softmax over 64 positions
    if (tid < 128) {
        int pl = tid >> 6, l = tid & 63;
        int len = lengths[blockIdx.x * 2 + pl];
        const float* ss = sc + pl * 64;
        float mx = -1e30f;
        for (int j = 0; j < 64; j++) if (j < len) mx = fmaxf(mx, ss[j]);
        float sum = 0.f;
        for (int j = 0; j < 64; j++) if (j < len) sum += expf(ss[j] - mx);
        float w = (l < len) ? expf(ss[l] - mx) / sum : 0.f;
        ((float*)(smem + OFF_WTS))[tid] = w;
    }
    __syncthreads();

    // weighted sum of X rows (fp16 in SMEM) -> paths_fea
    const float* wts = (const float*)(smem + OFF_WTS);
#pragma unroll
    for (int it = 0; it < 2; it++) {
        int pl = tid >> 7;
        int dp = (tid & 127) + it * 128;       // fp16x2 column (0..255)
        float a0 = 0.f, a1 = 0.f;
        const char* base = smem + OFF_XS + dp * 4;
#pragma unroll 8
        for (int l = 0; l < 64; l++) {
            int m = pl * 64 + l;
            uint32_t v = *(const uint32_t*)(base + m * XSTRIDE);
            __half2 hv = *(__half2*)&v;
            float wl = wts[m];
            a0 = fmaf(wl, __half2float(hv.x), a0);
            a1 = fmaf(wl, __half2float(hv.y), a1);
        }
        float* dst = g_pf + ((size_t)blockIdx.x * 2 + pl) * 512 + dp * 2;
        dst[0] = a0;
        dst[1] = a1;
    }
}

// ---------------- kernel 2: path-level MLP logits (M=64, grid 64) -------------
__global__ void __launch_bounds__(256, 1)
k_agg(const float* __restrict__ ab1, const float* __restrict__ aw2,
      const float* __restrict__ ab2) {
    extern __shared__ char smem[];
    uint32_t sb = smem_u32(smem);
    int tid = threadIdx.x;

    gemm_preamble<8, OFFWS_AGG>(g_aW1T, sb);

    float* b1s = (float*)(smem + OFF_B1);
    float* w2s = (float*)(smem + OFF_W2);
    float* sc  = (float*)(smem + OFF_SC);
    for (int i = tid; i < 512; i += 256) { b1s[i] = ab1[i]; w2s[i] = aw2[i]; }
    if (tid < 64) sc[tid] = 0.f;

    const float* X = g_pf + (size_t)blockIdx.x * 64 * 512;
    load_X_f16<64>(X, smem);

    gemm_mainloop<1, 8, OFFWS_AGG>(smem, sb, g_aW1T);

    if (tid < 64) g_a[blockIdx.x * 64 + tid] = sc[tid] + ab2[0];
}

// ---------------- kernel 3: softmax over 4096 paths ---------------------------
__global__ void k_soft() {
    __shared__ float red[1024];
    int t = threadIdx.x;
    float m = -1e30f;
    for (int i = t; i < NPATHS; i += 1024) m = fmaxf(m, g_a[i]);
    red[t] = m;
    __syncthreads();
    for (int s = 512; s > 0; s >>= 1) {
        if (t < s) red[t] = fmaxf(red[t], red[t + s]);
        __syncthreads();
    }
    float M = red[0];
    __syncthreads();
    float sum = 0.f;
    for (int i = t; i < NPATHS; i += 1024) sum += expf(g_a[i] - M);
    red[t] = sum;
    __syncthreads();
    for (int s = 512; s > 0; s >>= 1) {
        if (t < s) red[t] += red[t + s];
        __syncthreads();
    }
    float S = red[0];
    for (int i = t; i < NPATHS; i += 1024) g_aw[i] = expf(g_a[i] - M) / S;
}

// ---------------- kernel 4: partial weighted sums -----------------------------
__global__ void k_red() {
    int b = blockIdx.x, t = threadIdx.x;
    float a0 = 0.f, a1 = 0.f;
    for (int p = 0; p < 64; p++) {
        int pg = b * 64 + p;
        float w = g_aw[pg];
        const float* row = g_pf + (size_t)pg * 512;
        a0 = fmaf(w, row[t], a0);
        a1 = fmaf(w, row[t + 256], a1);
    }
    g_part[(size_t)b * 512 + t] = a0;
    g_part[(size_t)b * 512 + t + 256] = a1;
}

// ---------------- kernel 5: final reduction -----------------------------------
__global__ void k_fin(float* __restrict__ out) {
    int t = threadIdx.x;
    float s = 0.f;
    for (int b = 0; b < 64; b++) s += g_part[(size_t)b * 512 + t];
    out[t] = s;
}

// ---------------- entry -------------------------------------------------------
extern "C" void kernel_launch(void* const* d_in, const int* in_sizes, int n_in,
                              void* d_out, int out_size) {
    const float* nodes   = (const float*)d_in[0];
    const int*   lengths = (const int*)  d_in[1];
    const float* pW1     = (const float*)d_in[2];
    const float* pb1     = (const float*)d_in[3];
    const float* pw2     = (const float*)d_in[4];
    const float* pb2     = (const float*)d_in[5];
    const float* aW1     = (const float*)d_in[6];
    const float* ab1     = (const float*)d_in[7];
    const float* aw2     = (const float*)d_in[8];
    const float* ab2     = (const float*)d_in[9];
    float* out = (float*)d_out;

    cudaFuncSetAttribute(k_path, cudaFuncAttributeMaxDynamicSharedMemorySize, SMEM_PATH);
    cudaFuncSetAttribute(k_agg,  cudaFuncAttributeMaxDynamicSharedMemorySize, SMEM_AGG);

    __half* w1t;  cudaGetSymbolAddress((void**)&w1t,  g_W1T);
    __half* aw1t; cudaGetSymbolAddress((void**)&aw1t, g_aW1T);

    k_conv<<<dim3(8, 8), 256>>>(pW1, w1t);     // launch 0
    k_conv<<<dim3(8, 8), 256>>>(aW1, aw1t);    // launch 1
    k_path<<<NPATHS / 2, 256, SMEM_PATH>>>(nodes, lengths, pb1, pw2, pb2);  // 2
    k_agg<<<NPATHS / 64, 256, SMEM_AGG>>>(ab1, aw2, ab2);                   // 3
    k_soft<<<1, 1024>>>();
    k_red<<<64, 256>>>();
    k_fin<<<1, 512>>>(out);
}

// round 7
// speedup vs baseline: 1.4698x; 1.1089x over previous
#include <cuda_runtime.h>
#include <cuda_fp16.h>
#include <cstdint>
#include <cstddef>

// ============================================================================
// AttentionNetwork: P=4096, LMAX=64, D=512, H=512  (fp16 mma.sync path)
// R7: k_path re-tiled to warp tile 64x64 (128B LDSM per MMA, A re-read 2x),
// 4-deep ring of 256x32 W chunks with ONE barrier per iteration, and the
// X fp32->fp16 load pipelined into the first N-chunk's iterations.
// k_agg unchanged from R6 (M=64, full wave, 27.5us).
// ============================================================================

#define NPATHS 4096

// ---------------- device scratch --------------------------------------------
__device__ __half g_W1T[512 * 512];   // pW1^T  [n][k]
__device__ __half g_aW1T[512 * 512];  // aW1^T  [n][k]
__device__ float g_pf[NPATHS * 512];  // paths_fea
__device__ float g_a[NPATHS];         // path logits
__device__ float g_aw[NPATHS];        // path softmax weights
__device__ float g_part[64 * 512];    // reduction partials

// ---------------- SMEM layout (bytes) ----------------------------------------
#define OFF_SC   0            // 128 floats
#define OFF_WTS  512          // 128 floats
#define OFF_B1   1024         // 512 floats
#define OFF_W2   3072         // 512 floats
#define OFF_XS   5120         // X tile: ROWS x 1040B
#define XSTRIDE  1040
#define WSTRIDE  144          // k_agg W row stride (R6 layout)

// k_path (R7): X 128 rows; W ring: 4 bufs x (256n x 32k, stride 80B) = 81920
#define OFFWS_P   138240                    // 5120 + 128*1040
#define WSTRIDE_P 80
#define WSBUF_P   20480                     // 256*80
#define SMEM_PATH (138240 + 4 * 20480)      // 220160
// k_agg (R6): 64 X rows, NP=8 (W chunk 256x64, buf 36864), 4 bufs
#define OFFWS_AGG 71680                     // 5120 + 64*1040
#define SMEM_AGG  (71680 + 4 * 36864)       // 219136

// ---------------- PTX helpers ------------------------------------------------
__device__ __forceinline__ uint32_t smem_u32(const void* p) {
    uint32_t a;
    asm("{ .reg .u64 t; cvta.to.shared.u64 t, %1; cvt.u32.u64 %0, t; }"
        : "=r"(a) : "l"(p));
    return a;
}

__device__ __forceinline__ void ldsm4(uint32_t* r, uint32_t addr) {
    asm volatile("ldmatrix.sync.aligned.m8n8.x4.shared.b16 {%0,%1,%2,%3}, [%4];"
                 : "=r"(r[0]), "=r"(r[1]), "=r"(r[2]), "=r"(r[3]) : "r"(addr));
}

__device__ __forceinline__ void mma_f16(float* c, const uint32_t* a,
                                        uint32_t b0, uint32_t b1) {
    asm volatile(
        "mma.sync.aligned.m16n8k16.row.col.f32.f16.f16.f32 "
        "{%0,%1,%2,%3}, {%4,%5,%6,%7}, {%8,%9}, {%0,%1,%2,%3};"
        : "+f"(c[0]), "+f"(c[1]), "+f"(c[2]), "+f"(c[3])
        : "r"(a[0]), "r"(a[1]), "r"(a[2]), "r"(a[3]), "r"(b0), "r"(b1));
}

#define CP_ASYNC16(dst, src) \
    asm volatile("cp.async.cg.shared.global [%0], [%1], 16;" \
                 :: "r"(dst), "l"(src) : "memory")
#define CP_COMMIT() asm volatile("cp.async.commit_group;" ::: "memory")
#define CP_WAIT(n)  asm volatile("cp.async.wait_group %0;" :: "n"(n) : "memory")

// ============================================================================
//                       k_path (R7) building blocks
// ============================================================================

// prefetch W chunk s (= nc*16 + kc): 256 n-rows x 32 k -> ring buf
__device__ __forceinline__ void prefetch_Wp(const __half* __restrict__ Wt,
                                            int s, int buf, uint32_t sb) {
    int tid = threadIdx.x;
    int nc = s >> 4, kc = s & 15;
    const __half* src = Wt + (size_t)(nc * 256) * 512 + kc * 32;
#pragma unroll
    for (int i = 0; i < 4; i++) {
        int idx = tid + i * 256;          // 0..1023 16B slots
        int nl = idx >> 2;                // 4 x 16B per row
        int q  = idx & 3;
        uint32_t dst = sb + OFFWS_P + buf * WSBUF_P + nl * WSTRIDE_P + q * 16;
        CP_ASYNC16(dst, src + (size_t)nl * 512 + q * 8);
    }
    CP_COMMIT();
}

// convert one float4 -> 8B (2x half2) and store to SMEM
__device__ __forceinline__ void sts_f16x4(char* smem, uint32_t off, float4 v) {
    __half2 p0, p1;
    p0.x = __float2half_rn(v.x); p0.y = __float2half_rn(v.y);
    p1.x = __float2half_rn(v.z); p1.y = __float2half_rn(v.w);
    uint2 st;
    st.x = *(uint32_t*)&p0;
    st.y = *(uint32_t*)&p1;
    *(uint2*)(smem + off) = st;
}

// ============================================================================
//                       k_agg (R6) building blocks
// ============================================================================

template <int ROWS>
__device__ __forceinline__ void load_X_f16(const float* __restrict__ src,
                                           char* smem) {
    int tid = threadIdx.x;
#pragma unroll 4
    for (int i = 0; i < ROWS / 2; i++) {
        int idx = tid + i * 256;
        int m = idx >> 7;
        int q = idx & 127;
        float4 v = *(const float4*)(src + (size_t)m * 512 + q * 4);
        sts_f16x4(smem, OFF_XS + m * XSTRIDE + q * 8, v);
    }
}

template <int NP, int OFFWS>
__device__ __forceinline__ void prefetch_W(const __half* __restrict__ Wt,
                                           int s, int buf, uint32_t sb) {
    constexpr int WSBUF = NP * 32 * WSTRIDE;
    int tid = threadIdx.x;
    int nc = s >> 3, kc = s & 7;
    const __half* src = Wt + (size_t)(nc * NP * 32) * 512 + kc * 64;
#pragma unroll
    for (int i = 0; i < NP; i++) {
        int idx = tid + i * 256;
        int nl = idx >> 3;
        int q  = idx & 7;
        uint32_t dst = sb + OFFWS + buf * WSBUF + nl * WSTRIDE + q * 16;
        CP_ASYNC16(dst, src + (size_t)nl * 512 + q * 8);
    }
    CP_COMMIT();
}

template <int NP, int OFFWS>
__device__ __forceinline__ void gemm_preamble(const __half* __restrict__ Wt,
                                              uint32_t sb) {
    prefetch_W<NP, OFFWS>(Wt, 0, 0, sb);
    prefetch_W<NP, OFFWS>(Wt, 1, 1, sb);
    prefetch_W<NP, OFFWS>(Wt, 2, 2, sb);
}

// R6 mainloop (used by k_agg only): warp tile 64x32
template <int MP, int NP, int OFFWS>
__device__ __forceinline__ void gemm_mainloop(char* smem, uint32_t sb,
                                              const __half* __restrict__ Wt) {
    constexpr int WSBUF = NP * 32 * WSTRIDE;
    constexpr int S = (512 / (NP * 32)) * 8;
    int tid = threadIdx.x;
    int lane = tid & 31, wid = tid >> 5;
    int m_part = (MP == 1) ? 0 : (wid & (MP - 1));
    int n_part = wid / MP;
    const float* b1s = (const float*)(smem + OFF_B1);
    const float* w2s = (const float*)(smem + OFF_W2);
    float* sc = (float*)(smem + OFF_SC);

    int lr = lane & 7;
    uint32_t aA[4];
#pragma unroll
    for (int mi = 0; mi < 4; mi++)
        aA[mi] = sb + OFF_XS +
                 (m_part * 64 + mi * 16 + ((lane >> 3) & 1) * 8 + lr) * XSTRIDE +
                 (lane >> 4) * 16;
    uint32_t bA[2];
#pragma unroll
    for (int nj = 0; nj < 2; nj++)
        bA[nj] = sb + OFFWS +
                 (n_part * 32 + nj * 16 + (lane >> 4) * 8 + lr) * WSTRIDE +
                 ((lane >> 3) & 1) * 16;

    float acc[4][4][4];
#pragma unroll
    for (int mi = 0; mi < 4; mi++)
#pragma unroll
        for (int nq = 0; nq < 4; nq++)
#pragma unroll
            for (int q = 0; q < 4; q++) acc[mi][nq][q] = 0.f;
    float rs[8];
#pragma unroll
    for (int i = 0; i < 8; i++) rs[i] = 0.f;

    for (int s = 0; s < S; s++) {
        __syncthreads();
        if (s + 3 < S) prefetch_W<NP, OFFWS>(Wt, s + 3, (s + 3) & 3, sb);
        else CP_COMMIT();
        CP_WAIT(3);
        __syncthreads();

        int kc = s & 7;
        uint32_t buf = (uint32_t)(s & 3) * WSBUF;
        uint32_t A[2][4][4], B[2][2][4];
        {
            uint32_t kx = kc * 128;
#pragma unroll
            for (int mi = 0; mi < 4; mi++) ldsm4(A[0][mi], aA[mi] + kx);
#pragma unroll
            for (int nj = 0; nj < 2; nj++) ldsm4(B[0][nj], bA[nj] + buf);
        }
#pragma unroll
        for (int k16 = 0; k16 < 4; k16++) {
            int cur = k16 & 1, nxt = cur ^ 1;
            if (k16 < 3) {
                uint32_t kxX = kc * 128 + (k16 + 1) * 32;
                uint32_t kxW = (k16 + 1) * 32;
#pragma unroll
                for (int mi = 0; mi < 4; mi++) ldsm4(A[nxt][mi], aA[mi] + kxX);
#pragma unroll
                for (int nj = 0; nj < 2; nj++) ldsm4(B[nxt][nj], bA[nj] + buf + kxW);
            }
#pragma unroll
            for (int mi = 0; mi < 4; mi++)
#pragma unroll
                for (int nj = 0; nj < 2; nj++) {
                    mma_f16(acc[mi][nj * 2],     A[cur][mi], B[cur][nj][0], B[cur][nj][1]);
                    mma_f16(acc[mi][nj * 2 + 1], A[cur][mi], B[cur][nj][2], B[cur][nj][3]);
                }
        }

        if ((s & 7) == 7) {
            int nc = s >> 3;
            int t2 = (lane & 3) * 2;
#pragma unroll
            for (int mi = 0; mi < 4; mi++)
#pragma unroll
                for (int nq = 0; nq < 4; nq++) {
                    int n0 = nc * (NP * 32) + n_part * 32 + nq * 8 + t2;
                    float bb0 = b1s[n0], bb1 = b1s[n0 + 1];
                    float ww0 = w2s[n0], ww1 = w2s[n0 + 1];
                    float* cc = acc[mi][nq];
                    rs[mi * 2 + 0] += fmaxf(cc[0] + bb0, 0.f) * ww0 +
                                      fmaxf(cc[1] + bb1, 0.f) * ww1;
                    rs[mi * 2 + 1] += fmaxf(cc[2] + bb0, 0.f) * ww0 +
                                      fmaxf(cc[3] + bb1, 0.f) * ww1;
                    cc[0] = cc[1] = cc[2] = cc[3] = 0.f;
                }
        }
    }

#pragma unroll
    for (int i = 0; i < 8; i++) {
        rs[i] += __shfl_xor_sync(0xffffffffu, rs[i], 1);
        rs[i] += __shfl_xor_sync(0xffffffffu, rs[i], 2);
    }
    if ((lane & 3) == 0) {
        int g = lane >> 2;
#pragma unroll
        for (int mi = 0; mi < 4; mi++) {
            atomicAdd(&sc[m_part * 64 + mi * 16 + g],     rs[mi * 2 + 0]);
            atomicAdd(&sc[m_part * 64 + mi * 16 + 8 + g], rs[mi * 2 + 1]);
        }
    }
    __syncthreads();
}

// ---------------- kernel 0: transpose + convert weights ----------------------
__global__ void k_conv(const float* __restrict__ src, __half* __restrict__ dst) {
    __shared__ float tile[64][65];
    int k0 = blockIdx.y * 64, n0 = blockIdx.x * 64;
    for (int i = threadIdx.x; i < 4096; i += 256) {
        int r = i >> 6, cth = i & 63;
        tile[r][cth] = src[(size_t)(k0 + r) * 512 + n0 + cth];
    }
    __syncthreads();
    for (int i = threadIdx.x; i < 4096; i += 256) {
        int r = i >> 6, cth = i & 63;
        dst[(size_t)(n0 + r) * 512 + k0 + cth] = __float2half_rn(tile[cth][r]);
    }
}

// ---------------- kernel 1: fused per-2-path stage (R7 tiling) ----------------
__global__ void __launch_bounds__(256, 1)
k_path(const float* __restrict__ nodes, const int* __restrict__ lengths,
       const float* __restrict__ pb1, const float* __restrict__ pw2,
       const float* __restrict__ pb2) {
    extern __shared__ char smem[];
    uint32_t sb = smem_u32(smem);
    int tid = threadIdx.x;
    int lane = tid & 31, wid = tid >> 5;
    int m_part = wid & 1;                 // 64-row M slice
    int n_part = wid >> 1;                // 64-col slice of 256-N-chunk

    // W chunks start streaming immediately
    prefetch_Wp(g_W1T, 0, 0, sb);
    prefetch_Wp(g_W1T, 1, 1, sb);
    prefetch_Wp(g_W1T, 2, 2, sb);

    float* b1s = (float*)(smem + OFF_B1);
    float* w2s = (float*)(smem + OFF_W2);
    float* sc  = (float*)(smem + OFF_SC);
    for (int i = tid; i < 512; i += 256) { b1s[i] = pb1[i]; w2s[i] = pw2[i]; }
    if (tid < 128) sc[tid] = 0.f;

    const float* X = nodes + (size_t)blockIdx.x * 128 * 512;

    // preload X slice 0 (k in [0,32))
#pragma unroll
    for (int i = 0; i < 4; i++) {
        int idx = tid + i * 256;          // 0..1023 float4 slots of slice
        int m = idx >> 3;                 // 8 float4 per slice-row
        int q = idx & 7;
        float4 v = *(const float4*)(X + (size_t)m * 512 + q * 4);
        sts_f16x4(smem, OFF_XS + m * XSTRIDE + q * 8, v);
    }

    // per-lane ldmatrix bases
    int lr = lane & 7;
    uint32_t aA[4];
#pragma unroll
    for (int mi = 0; mi < 4; mi++)
        aA[mi] = sb + OFF_XS +
                 (m_part * 64 + mi * 16 + ((lane >> 3) & 1) * 8 + lr) * XSTRIDE +
                 (lane >> 4) * 16;
    uint32_t bA[4];
#pragma unroll
    for (int nj = 0; nj < 4; nj++)
        bA[nj] = sb + OFFWS_P +
                 (n_part * 64 + nj * 16 + (lane >> 4) * 8 + lr) * WSTRIDE_P +
                 ((lane >> 3) & 1) * 16;

    float acc[4][8][4];                   // 128 accumulator regs
#pragma unroll
    for (int mi = 0; mi < 4; mi++)
#pragma unroll
        for (int nq = 0; nq < 8; nq++)
#pragma unroll
            for (int q = 0; q < 4; q++) acc[mi][nq][q] = 0.f;
    float rs[8];
#pragma unroll
    for (int i = 0; i < 8; i++) rs[i] = 0.f;

    // mainloop: 32 iters = 2 N-chunks x 16 k-chunks (32 k each), 1 barrier/iter
    for (int s = 0; s < 32; s++) {
        CP_WAIT(2);                       // W chunk s landed (3 groups ahead)
        __syncthreads();                  // visible + ring slot (s-1) free
        if (s + 3 < 32) prefetch_Wp(g_W1T, s + 3, (s + 3) & 3, sb);
        else CP_COMMIT();

        // during N-chunk 0: fetch X slice s+1 (used at iter s+1)
        float4 xv0, xv1, xv2, xv3;
        bool xload = (s < 15);
        if (xload) {
            const float* xsrc = X + (s + 1) * 32;
            int idx0 = tid;
            xv0 = *(const float4*)(xsrc + (size_t)(idx0 >> 3) * 512 + (idx0 & 7) * 4);
            int idx1 = tid + 256;
            xv1 = *(const float4*)(xsrc + (size_t)(idx1 >> 3) * 512 + (idx1 & 7) * 4);
            int idx2 = tid + 512;
            xv2 = *(const float4*)(xsrc + (size_t)(idx2 >> 3) * 512 + (idx2 & 7) * 4);
            int idx3 = tid + 768;
            xv3 = *(const float4*)(xsrc + (size_t)(idx3 >> 3) * 512 + (idx3 & 7) * 4);
        }

        int kc = s & 15;
        uint32_t buf = (uint32_t)(s & 3) * WSBUF_P;
#pragma unroll
        for (int k16 = 0; k16 < 2; k16++) {
            uint32_t kxX = kc * 64 + k16 * 32;
            uint32_t kxW = k16 * 32;
            uint32_t A[4][4], B[4][4];
#pragma unroll
            for (int mi = 0; mi < 4; mi++) ldsm4(A[mi], aA[mi] + kxX);
#pragma unroll
            for (int nj = 0; nj < 4; nj++) ldsm4(B[nj], bA[nj] + buf + kxW);
#pragma unroll
            for (int mi = 0; mi < 4; mi++)
#pragma unroll
                for (int nj = 0; nj < 4; nj++) {
                    mma_f16(acc[mi][nj * 2],     A[mi], B[nj][0], B[nj][1]);
                    mma_f16(acc[mi][nj * 2 + 1], A[mi], B[nj][2], B[nj][3]);
                }
        }

        if (xload) {
            uint32_t base = OFF_XS + (s + 1) * 64;
            int idx0 = tid;
            sts_f16x4(smem, base + (idx0 >> 3) * XSTRIDE + (idx0 & 7) * 8, xv0);
            int idx1 = tid + 256;
            sts_f16x4(smem, base + (idx1 >> 3) * XSTRIDE + (idx1 & 7) * 8, xv1);
            int idx2 = tid + 512;
            sts_f16x4(smem, base + (idx2 >> 3) * XSTRIDE + (idx2 & 7) * 8, xv2);
            int idx3 = tid + 768;
            sts_f16x4(smem, base + (idx3 >> 3) * XSTRIDE + (idx3 & 7) * 8, xv3);
        }

        if (kc == 15) {
            // fold this 256-wide N chunk into per-row score partials
            int nc = s >> 4;
            int t2 = (lane & 3) * 2;
#pragma unroll
            for (int mi = 0; mi < 4; mi++)
#pragma unroll
                for (int nq = 0; nq < 8; nq++) {
                    int n0 = nc * 256 + n_part * 64 + nq * 8 + t2;
                    float bb0 = b1s[n0], bb1 = b1s[n0 + 1];
                    float ww0 = w2s[n0], ww1 = w2s[n0 + 1];
                    float* cc = acc[mi][nq];
                    rs[mi * 2 + 0] += fmaxf(cc[0] + bb0, 0.f) * ww0 +
                                      fmaxf(cc[1] + bb1, 0.f) * ww1;
                    rs[mi * 2 + 1] += fmaxf(cc[2] + bb0, 0.f) * ww0 +
                                      fmaxf(cc[3] + bb1, 0.f) * ww1;
                    cc[0] = cc[1] = cc[2] = cc[3] = 0.f;
                }
        }
    }

    // reduce the 4 lanes sharing each row, combine the 4 N-part warps
#pragma unroll
    for (int i = 0; i < 8; i++) {
        rs[i] += __shfl_xor_sync(0xffffffffu, rs[i], 1);
        rs[i] += __shfl_xor_sync(0xffffffffu, rs[i], 2);
    }
    if ((lane & 3) == 0) {
        int g = lane >> 2;
#pragma unroll
        for (int mi = 0; mi < 4; mi++) {
            atomicAdd(&sc[m_part * 64 + mi * 16 + g],     rs[mi * 2 + 0]);
            atomicAdd(&sc[m_part * 64 + mi * 16 + 8 + g], rs[mi * 2 + 1]);
        }
    }
    __syncthreads();

    // per-path masked softmax over 64 positions
    if (tid < 128) {
        int pl = tid >> 6, l = tid & 63;
        int len = lengths[blockIdx.x * 2 + pl];
        const float* ss = sc + pl * 64;
        float mx = -1e30f;
        for (int j = 0; j < 64; j++) if (j < len) mx = fmaxf(mx, ss[j]);
        float sum = 0.f;
        for (int j = 0; j < 64; j++) if (j < len) sum += expf(ss[j] - mx);
        float w = (l < len) ? expf(ss[l] - mx) / sum : 0.f;
        ((float*)(smem + OFF_WTS))[tid] = w;
    }
    __syncthreads();

    // weighted sum of X rows (fp16 in SMEM) -> paths_fea
    const float* wts = (const float*)(smem + OFF_WTS);
#pragma unroll
    for (int it = 0; it < 2; it++) {
        int pl = tid >> 7;
        int dp = (tid & 127) + it * 128;       // fp16x2 column (0..255)
        float a0 = 0.f, a1 = 0.f;
        const char* base = smem + OFF_XS + dp * 4;
#pragma unroll 8
        for (int l = 0; l < 64; l++) {
            int m = pl * 64 + l;
            uint32_t v = *(const uint32_t*)(base + m * XSTRIDE);
            __half2 hv = *(__half2*)&v;
            float wl = wts[m];
            a0 = fmaf(wl, __half2float(hv.x), a0);
            a1 = fmaf(wl, __half2float(hv.y), a1);
        }
        float* dst = g_pf + ((size_t)blockIdx.x * 2 + pl) * 512 + dp * 2;
        dst[0] = a0;
        dst[1] = a1;
    }
}

// ---------------- kernel 2: path-level MLP logits (M=64, grid 64) -------------
__global__ void __launch_bounds__(256, 1)
k_agg(const float* __restrict__ ab1, const float* __restrict__ aw2,
      const float* __restrict__ ab2) {
    extern __shared__ char smem[];
    uint32_t sb = smem_u32(smem);
    int tid = threadIdx.x;

    gemm_preamble<8, OFFWS_AGG>(g_aW1T, sb);

    float* b1s = (float*)(smem + OFF_B1);
    float* w2s = (float*)(smem + OFF_W2);
    float* sc  = (float*)(smem + OFF_SC);
    for (int i = tid; i < 512; i += 256) { b1s[i] = ab1[i]; w2s[i] = aw2[i]; }
    if (tid < 64) sc[tid] = 0.f;

    const float* X = g_pf + (size_t)blockIdx.x * 64 * 512;
    load_X_f16<64>(X, smem);

    gemm_mainloop<1, 8, OFFWS_AGG>(smem, sb, g_aW1T);

    if (tid < 64) g_a[blockIdx.x * 64 + tid] = sc[tid] + ab2[0];
}

// ---------------- kernel 3: softmax over 4096 paths ---------------------------
__global__ void k_soft() {
    __shared__ float red[1024];
    int t = threadIdx.x;
    float m = -1e30f;
    for (int i = t; i < NPATHS; i += 1024) m = fmaxf(m, g_a[i]);
    red[t] = m;
    __syncthreads();
    for (int s = 512; s > 0; s >>= 1) {
        if (t < s) red[t] = fmaxf(red[t], red[t + s]);
        __syncthreads();
    }
    float M = red[0];
    __syncthreads();
    float sum = 0.f;
    for (int i = t; i < NPATHS; i += 1024) sum += expf(g_a[i] - M);
    red[t] = sum;
    __syncthreads();
    for (int s = 512; s > 0; s >>= 1) {
        if (t < s) red[t] += red[t + s];
        __syncthreads();
    }
    float S = red[0];
    for (int i = t; i < NPATHS; i += 1024) g_aw[i] = expf(g_a[i] - M) / S;
}

// ---------------- kernel 4: partial weighted sums -----------------------------
__global__ void k_red() {
    int b = blockIdx.x, t = threadIdx.x;
    float a0 = 0.f, a1 = 0.f;
    for (int p = 0; p < 64; p++) {
        int pg = b * 64 + p;
        float w = g_aw[pg];
        const float* row = g_pf + (size_t)pg * 512;
        a0 = fmaf(w, row[t], a0);
        a1 = fmaf(w, row[t + 256], a1);
    }
    g_part[(size_t)b * 512 + t] = a0;
    g_part[(size_t)b * 512 + t + 256] = a1;
}

// ---------------- kernel 5: final reduction -----------------------------------
__global__ void k_fin(float* __restrict__ out) {
    int t = threadIdx.x;
    float s = 0.f;
    for (int b = 0; b < 64; b++) s += g_part[(size_t)b * 512 + t];
    out[t] = s;
}

// ---------------- entry -------------------------------------------------------
extern "C" void kernel_launch(void* const* d_in, const int* in_sizes, int n_in,
                              void* d_out, int out_size) {
    const float* nodes   = (const float*)d_in[0];
    const int*   lengths = (const int*)  d_in[1];
    const float* pW1     = (const float*)d_in[2];
    const float* pb1     = (const float*)d_in[3];
    const float* pw2     = (const float*)d_in[4];
    const float* pb2     = (const float*)d_in[5];
    const float* aW1     = (const float*)d_in[6];
    const float* ab1     = (const float*)d_in[7];
    const float* aw2     = (const float*)d_in[8];
    const float* ab2     = (const float*)d_in[9];
    float* out = (float*)d_out;

    cudaFuncSetAttribute(k_path, cudaFuncAttributeMaxDynamicSharedMemorySize, SMEM_PATH);
    cudaFuncSetAttribute(k_agg,  cudaFuncAttributeMaxDynamicSharedMemorySize, SMEM_AGG);

    __half* w1t;  cudaGetSymbolAddress((void**)&w1t,  g_W1T);
    __half* aw1t; cudaGetSymbolAddress((void**)&aw1t, g_aW1T);

    k_conv<<<dim3(8, 8), 256>>>(pW1, w1t);     // launch 0
    k_conv<<<dim3(8, 8), 256>>>(aW1, aw1t);    // launch 1
    k_path<<<NPATHS / 2, 256, SMEM_PATH>>>(nodes, lengths, pb1, pw2, pb2);  // 2
    k_agg<<<NPATHS / 64, 256, SMEM_AGG>>>(ab1, aw2, ab2);                   // 3
    k_soft<<<1, 1024>>>();
    k_red<<<64, 256>>>();
    k_fin<<<1, 512>>>(out);
}

// round 8
// speedup vs baseline: 1.4845x; 1.0100x over previous
#include <cuda_runtime.h>
#include <cuda_fp16.h>
#include <cstdint>
#include <cstddef>

// ============================================================================
// AttentionNetwork: P=4096, LMAX=64, D=512, H=512  (fp16 mma.sync path)
// R8: k_path M=64 (1 path per CTA), SMEM 112.6KB -> 2 CTAs/SM. Cross-CTA
// overlap hides the latency/barrier stalls that pinned issue at ~15%.
// Warp tile 32x64, 2-buffer W ring of 256n x 32k chunks.
// ============================================================================

#define NPATHS 4096

// ---------------- device scratch --------------------------------------------
__device__ __half g_W1T[512 * 512];   // pW1^T  [n][k]
__device__ __half g_aW1T[512 * 512];  // aW1^T  [n][k]
__device__ float g_pf[NPATHS * 512];  // paths_fea
__device__ float g_a[NPATHS];         // path logits
__device__ float g_aw[NPATHS];        // path softmax weights
__device__ float g_part[64 * 512];    // reduction partials

// ---------------- SMEM layout (bytes) ----------------------------------------
#define OFF_SC   0            // scores (<=128 floats)
#define OFF_WTS  512          // softmax weights
#define OFF_B1   1024         // 512 floats
#define OFF_W2   3072         // 512 floats
#define OFF_XS   5120         // X tile: ROWS x 1040B
#define XSTRIDE  1040
#define WSTRIDE  144          // k_agg W row stride (R6 layout)

// k_path (R8): X 64 rows (66560); W ring: 2 bufs x (256n x 32k, stride 80B)
#define OFFWS_P   71680                     // 5120 + 64*1040
#define WSTRIDE_P 80
#define WSBUF_P   20480                     // 256*80
#define SMEM_PATH (71680 + 2 * 20480)       // 112640 -> 2 CTAs/SM
// k_agg (R6): 64 X rows, NP=8 (W chunk 256x64, buf 36864), 4 bufs
#define OFFWS_AGG 71680
#define SMEM_AGG  (71680 + 4 * 36864)       // 219136

// ---------------- PTX helpers ------------------------------------------------
__device__ __forceinline__ uint32_t smem_u32(const void* p) {
    uint32_t a;
    asm("{ .reg .u64 t; cvta.to.shared.u64 t, %1; cvt.u32.u64 %0, t; }"
        : "=r"(a) : "l"(p));
    return a;
}

__device__ __forceinline__ void ldsm4(uint32_t* r, uint32_t addr) {
    asm volatile("ldmatrix.sync.aligned.m8n8.x4.shared.b16 {%0,%1,%2,%3}, [%4];"
                 : "=r"(r[0]), "=r"(r[1]), "=r"(r[2]), "=r"(r[3]) : "r"(addr));
}

__device__ __forceinline__ void mma_f16(float* c, const uint32_t* a,
                                        uint32_t b0, uint32_t b1) {
    asm volatile(
        "mma.sync.aligned.m16n8k16.row.col.f32.f16.f16.f32 "
        "{%0,%1,%2,%3}, {%4,%5,%6,%7}, {%8,%9}, {%0,%1,%2,%3};"
        : "+f"(c[0]), "+f"(c[1]), "+f"(c[2]), "+f"(c[3])
        : "r"(a[0]), "r"(a[1]), "r"(a[2]), "r"(a[3]), "r"(b0), "r"(b1));
}

#define CP_ASYNC16(dst, src) \
    asm volatile("cp.async.cg.shared.global [%0], [%1], 16;" \
                 :: "r"(dst), "l"(src) : "memory")
#define CP_COMMIT() asm volatile("cp.async.commit_group;" ::: "memory")
#define CP_WAIT(n)  asm volatile("cp.async.wait_group %0;" :: "n"(n) : "memory")

// convert one float4 -> 8B (2x half2) and store to SMEM
__device__ __forceinline__ void sts_f16x4(char* smem, uint32_t off, float4 v) {
    __half2 p0, p1;
    p0.x = __float2half_rn(v.x); p0.y = __float2half_rn(v.y);
    p1.x = __float2half_rn(v.z); p1.y = __float2half_rn(v.w);
    uint2 st;
    st.x = *(uint32_t*)&p0;
    st.y = *(uint32_t*)&p1;
    *(uint2*)(smem + off) = st;
}

// ============================================================================
//                       k_path (R8) building blocks
// ============================================================================

// prefetch W chunk s (= nc*16 + kc): 256 n-rows x 32 k -> ring buf
__device__ __forceinline__ void prefetch_Wp(const __half* __restrict__ Wt,
                                            int s, int buf, uint32_t sb) {
    int tid = threadIdx.x;
    int nc = s >> 4, kc = s & 15;
    const __half* src = Wt + (size_t)(nc * 256) * 512 + kc * 32;
#pragma unroll
    for (int i = 0; i < 4; i++) {
        int idx = tid + i * 256;          // 0..1023 16B slots
        int nl = idx >> 2;                // 4 x 16B per row
        int q  = idx & 3;
        uint32_t dst = sb + OFFWS_P + buf * WSBUF_P + nl * WSTRIDE_P + q * 16;
        CP_ASYNC16(dst, src + (size_t)nl * 512 + q * 8);
    }
    CP_COMMIT();
}

// ============================================================================
//                       k_agg (R6) building blocks
// ============================================================================

template <int ROWS>
__device__ __forceinline__ void load_X_f16(const float* __restrict__ src,
                                           char* smem) {
    int tid = threadIdx.x;
#pragma unroll 4
    for (int i = 0; i < ROWS / 2; i++) {
        int idx = tid + i * 256;
        int m = idx >> 7;
        int q = idx & 127;
        float4 v = *(const float4*)(src + (size_t)m * 512 + q * 4);
        sts_f16x4(smem, OFF_XS + m * XSTRIDE + q * 8, v);
    }
}

template <int NP, int OFFWS>
__device__ __forceinline__ void prefetch_W(const __half* __restrict__ Wt,
                                           int s, int buf, uint32_t sb) {
    constexpr int WSBUF = NP * 32 * WSTRIDE;
    int tid = threadIdx.x;
    int nc = s >> 3, kc = s & 7;
    const __half* src = Wt + (size_t)(nc * NP * 32) * 512 + kc * 64;
#pragma unroll
    for (int i = 0; i < NP; i++) {
        int idx = tid + i * 256;
        int nl = idx >> 3;
        int q  = idx & 7;
        uint32_t dst = sb + OFFWS + buf * WSBUF + nl * WSTRIDE + q * 16;
        CP_ASYNC16(dst, src + (size_t)nl * 512 + q * 8);
    }
    CP_COMMIT();
}

// R6 mainloop (k_agg): warp tile 64x32
template <int MP, int NP, int OFFWS>
__device__ __forceinline__ void gemm_mainloop(char* smem, uint32_t sb,
                                              const __half* __restrict__ Wt) {
    constexpr int WSBUF = NP * 32 * WSTRIDE;
    constexpr int S = (512 / (NP * 32)) * 8;
    int tid = threadIdx.x;
    int lane = tid & 31, wid = tid >> 5;
    int m_part = (MP == 1) ? 0 : (wid & (MP - 1));
    int n_part = wid / MP;
    const float* b1s = (const float*)(smem + OFF_B1);
    const float* w2s = (const float*)(smem + OFF_W2);
    float* sc = (float*)(smem + OFF_SC);

    int lr = lane & 7;
    uint32_t aA[4];
#pragma unroll
    for (int mi = 0; mi < 4; mi++)
        aA[mi] = sb + OFF_XS +
                 (m_part * 64 + mi * 16 + ((lane >> 3) & 1) * 8 + lr) * XSTRIDE +
                 (lane >> 4) * 16;
    uint32_t bA[2];
#pragma unroll
    for (int nj = 0; nj < 2; nj++)
        bA[nj] = sb + OFFWS +
                 (n_part * 32 + nj * 16 + (lane >> 4) * 8 + lr) * WSTRIDE +
                 ((lane >> 3) & 1) * 16;

    float acc[4][4][4];
#pragma unroll
    for (int mi = 0; mi < 4; mi++)
#pragma unroll
        for (int nq = 0; nq < 4; nq++)
#pragma unroll
            for (int q = 0; q < 4; q++) acc[mi][nq][q] = 0.f;
    float rs[8];
#pragma unroll
    for (int i = 0; i < 8; i++) rs[i] = 0.f;

    for (int s = 0; s < S; s++) {
        __syncthreads();
        if (s + 3 < S) prefetch_W<NP, OFFWS>(Wt, s + 3, (s + 3) & 3, sb);
        else CP_COMMIT();
        CP_WAIT(3);
        __syncthreads();

        int kc = s & 7;
        uint32_t buf = (uint32_t)(s & 3) * WSBUF;
        uint32_t A[2][4][4], B[2][2][4];
        {
            uint32_t kx = kc * 128;
#pragma unroll
            for (int mi = 0; mi < 4; mi++) ldsm4(A[0][mi], aA[mi] + kx);
#pragma unroll
            for (int nj = 0; nj < 2; nj++) ldsm4(B[0][nj], bA[nj] + buf);
        }
#pragma unroll
        for (int k16 = 0; k16 < 4; k16++) {
            int cur = k16 & 1, nxt = cur ^ 1;
            if (k16 < 3) {
                uint32_t kxX = kc * 128 + (k16 + 1) * 32;
                uint32_t kxW = (k16 + 1) * 32;
#pragma unroll
                for (int mi = 0; mi < 4; mi++) ldsm4(A[nxt][mi], aA[mi] + kxX);
#pragma unroll
                for (int nj = 0; nj < 2; nj++) ldsm4(B[nxt][nj], bA[nj] + buf + kxW);
            }
#pragma unroll
            for (int mi = 0; mi < 4; mi++)
#pragma unroll
                for (int nj = 0; nj < 2; nj++) {
                    mma_f16(acc[mi][nj * 2],     A[cur][mi], B[cur][nj][0], B[cur][nj][1]);
                    mma_f16(acc[mi][nj * 2 + 1], A[cur][mi], B[cur][nj][2], B[cur][nj][3]);
                }
        }

        if ((s & 7) == 7) {
            int nc = s >> 3;
            int t2 = (lane & 3) * 2;
#pragma unroll
            for (int mi = 0; mi < 4; mi++)
#pragma unroll
                for (int nq = 0; nq < 4; nq++) {
                    int n0 = nc * (NP * 32) + n_part * 32 + nq * 8 + t2;
                    float bb0 = b1s[n0], bb1 = b1s[n0 + 1];
                    float ww0 = w2s[n0], ww1 = w2s[n0 + 1];
                    float* cc = acc[mi][nq];
                    rs[mi * 2 + 0] += fmaxf(cc[0] + bb0, 0.f) * ww0 +
                                      fmaxf(cc[1] + bb1, 0.f) * ww1;
                    rs[mi * 2 + 1] += fmaxf(cc[2] + bb0, 0.f) * ww0 +
                                      fmaxf(cc[3] + bb1, 0.f) * ww1;
                    cc[0] = cc[1] = cc[2] = cc[3] = 0.f;
                }
        }
    }

#pragma unroll
    for (int i = 0; i < 8; i++) {
        rs[i] += __shfl_xor_sync(0xffffffffu, rs[i], 1);
        rs[i] += __shfl_xor_sync(0xffffffffu, rs[i], 2);
    }
    if ((lane & 3) == 0) {
        int g = lane >> 2;
#pragma unroll
        for (int mi = 0; mi < 4; mi++) {
            atomicAdd(&sc[m_part * 64 + mi * 16 + g],     rs[mi * 2 + 0]);
            atomicAdd(&sc[m_part * 64 + mi * 16 + 8 + g], rs[mi * 2 + 1]);
        }
    }
    __syncthreads();
}

// ---------------- kernel 0: transpose + convert weights ----------------------
__global__ void k_conv(const float* __restrict__ src, __half* __restrict__ dst) {
    __shared__ float tile[64][65];
    int k0 = blockIdx.y * 64, n0 = blockIdx.x * 64;
    for (int i = threadIdx.x; i < 4096; i += 256) {
        int r = i >> 6, cth = i & 63;
        tile[r][cth] = src[(size_t)(k0 + r) * 512 + n0 + cth];
    }
    __syncthreads();
    for (int i = threadIdx.x; i < 4096; i += 256) {
        int r = i >> 6, cth = i & 63;
        dst[(size_t)(n0 + r) * 512 + k0 + cth] = __float2half_rn(tile[cth][r]);
    }
}

// ---------------- kernel 1: fused per-path stage (R8: M=64, occ 2) ------------
__global__ void __launch_bounds__(256, 2)
k_path(const float* __restrict__ nodes, const int* __restrict__ lengths,
       const float* __restrict__ pb1, const float* __restrict__ pw2,
       const float* __restrict__ pb2) {
    extern __shared__ char smem[];
    uint32_t sb = smem_u32(smem);
    int tid = threadIdx.x;
    int lane = tid & 31, wid = tid >> 5;
    int m_part = wid & 1;                 // 32-row M slice
    int n_part = wid >> 1;                // 64-col slice of 256-N-chunk

    // W chunks start streaming immediately
    prefetch_Wp(g_W1T, 0, 0, sb);
    prefetch_Wp(g_W1T, 1, 1, sb);

    float* b1s = (float*)(smem + OFF_B1);
    float* w2s = (float*)(smem + OFF_W2);
    float* sc  = (float*)(smem + OFF_SC);
    for (int i = tid; i < 512; i += 256) { b1s[i] = pb1[i]; w2s[i] = pw2[i]; }
    if (tid < 64) sc[tid] = 0.f;

    // load X: 64 rows x 512 fp32 -> fp16 SMEM
    const float* X = nodes + (size_t)blockIdx.x * 64 * 512;
    load_X_f16<64>(X, smem);

    // per-lane ldmatrix bases
    int lr = lane & 7;
    uint32_t aA[2];
#pragma unroll
    for (int mi = 0; mi < 2; mi++)
        aA[mi] = sb + OFF_XS +
                 (m_part * 32 + mi * 16 + ((lane >> 3) & 1) * 8 + lr) * XSTRIDE +
                 (lane >> 4) * 16;
    uint32_t bA[4];
#pragma unroll
    for (int nj = 0; nj < 4; nj++)
        bA[nj] = sb + OFFWS_P +
                 (n_part * 64 + nj * 16 + (lane >> 4) * 8 + lr) * WSTRIDE_P +
                 ((lane >> 3) & 1) * 16;

    float acc[2][8][4];                   // 64 accumulator regs
#pragma unroll
    for (int mi = 0; mi < 2; mi++)
#pragma unroll
        for (int nq = 0; nq < 8; nq++)
#pragma unroll
            for (int q = 0; q < 4; q++) acc[mi][nq][q] = 0.f;
    float rs[4] = {0.f, 0.f, 0.f, 0.f};

    // mainloop: 32 iters = 2 N-chunks x 16 k-chunks (32 k each)
    for (int s = 0; s < 32; s++) {
        if (s == 31) { CP_WAIT(0); } else { CP_WAIT(1); }   // chunk s landed
        __syncthreads();                  // visible to all warps (also X, iter0)

        int kc = s & 15;
        uint32_t buf = (uint32_t)(s & 1) * WSBUF_P;
#pragma unroll
        for (int k16 = 0; k16 < 2; k16++) {
            uint32_t kxX = kc * 64 + k16 * 32;
            uint32_t kxW = k16 * 32;
            uint32_t A[2][4], B[4][4];
#pragma unroll
            for (int mi = 0; mi < 2; mi++) ldsm4(A[mi], aA[mi] + kxX);
#pragma unroll
            for (int nj = 0; nj < 4; nj++) ldsm4(B[nj], bA[nj] + buf + kxW);
#pragma unroll
            for (int mi = 0; mi < 2; mi++)
#pragma unroll
                for (int nj = 0; nj < 4; nj++) {
                    mma_f16(acc[mi][nj * 2],     A[mi], B[nj][0], B[nj][1]);
                    mma_f16(acc[mi][nj * 2 + 1], A[mi], B[nj][2], B[nj][3]);
                }
        }

        if (kc == 15) {
            // fold this 256-wide N chunk into per-row score partials
            int nc = s >> 4;
            int t2 = (lane & 3) * 2;
#pragma unroll
            for (int mi = 0; mi < 2; mi++)
#pragma unroll
                for (int nq = 0; nq < 8; nq++) {
                    int n0 = nc * 256 + n_part * 64 + nq * 8 + t2;
                    float bb0 = b1s[n0], bb1 = b1s[n0 + 1];
                    float ww0 = w2s[n0], ww1 = w2s[n0 + 1];
                    float* cc = acc[mi][nq];
                    rs[mi * 2 + 0] += fmaxf(cc[0] + bb0, 0.f) * ww0 +
                                      fmaxf(cc[1] + bb1, 0.f) * ww1;
                    rs[mi * 2 + 1] += fmaxf(cc[2] + bb0, 0.f) * ww0 +
                                      fmaxf(cc[3] + bb1, 0.f) * ww1;
                    cc[0] = cc[1] = cc[2] = cc[3] = 0.f;
                }
        }

        __syncthreads();                  // all warps done reading buf[s&1]
        if (s + 2 < 32) prefetch_Wp(g_W1T, s + 2, s & 1, sb);
    }

    // reduce the 4 lanes sharing each row, combine the 4 N-part warps
#pragma unroll
    for (int i = 0; i < 4; i++) {
        rs[i] += __shfl_xor_sync(0xffffffffu, rs[i], 1);
        rs[i] += __shfl_xor_sync(0xffffffffu, rs[i], 2);
    }
    if ((lane & 3) == 0) {
        int g = lane >> 2;
#pragma unroll
        for (int mi = 0; mi < 2; mi++) {
            atomicAdd(&sc[m_part * 32 + mi * 16 + g],     rs[mi * 2 + 0]);
            atomicAdd(&sc[m_part * 32 + mi * 16 + 8 + g], rs[mi * 2 + 1]);
        }
    }
    __syncthreads();

    // masked softmax over this path's 64 positions
    if (tid < 64) {
        int len = lengths[blockIdx.x];
        float mx = -1e30f;
        for (int j = 0; j < 64; j++) if (j < len) mx = fmaxf(mx, sc[j]);
        float sum = 0.f;
        for (int j = 0; j < 64; j++) if (j < len) sum += expf(sc[j] - mx);
        float w = (tid < len) ? expf(sc[tid] - mx) / sum : 0.f;
        ((float*)(smem + OFF_WTS))[tid] = w;
    }
    __syncthreads();

    // weighted sum of X rows (fp16 in SMEM) -> paths_fea
    const float* wts = (const float*)(smem + OFF_WTS);
    {
        int dp = tid;                     // fp16x2 column (0..255)
        float a0 = 0.f, a1 = 0.f;
        const char* base = smem + OFF_XS + dp * 4;
#pragma unroll 8
        for (int l = 0; l < 64; l++) {
            uint32_t v = *(const uint32_t*)(base + l * XSTRIDE);
            __half2 hv = *(__half2*)&v;
            float wl = wts[l];
            a0 = fmaf(wl, __half2float(hv.x), a0);
            a1 = fmaf(wl, __half2float(hv.y), a1);
        }
        float* dst = g_pf + (size_t)blockIdx.x * 512 + dp * 2;
        dst[0] = a0;
        dst[1] = a1;
    }
}

// ---------------- kernel 2: path-level MLP logits (M=64, grid 64) -------------
__global__ void __launch_bounds__(256, 1)
k_agg(const float* __restrict__ ab1, const float* __restrict__ aw2,
      const float* __restrict__ ab2) {
    extern __shared__ char smem[];
    uint32_t sb = smem_u32(smem);
    int tid = threadIdx.x;

    prefetch_W<8, OFFWS_AGG>(g_aW1T, 0, 0, sb);
    prefetch_W<8, OFFWS_AGG>(g_aW1T, 1, 1, sb);
    prefetch_W<8, OFFWS_AGG>(g_aW1T, 2, 2, sb);

    float* b1s = (float*)(smem + OFF_B1);
    float* w2s = (float*)(smem + OFF_W2);
    float* sc  = (float*)(smem + OFF_SC);
    for (int i = tid; i < 512; i += 256) { b1s[i] = ab1[i]; w2s[i] = aw2[i]; }
    if (tid < 64) sc[tid] = 0.f;

    const float* X = g_pf + (size_t)blockIdx.x * 64 * 512;
    load_X_f16<64>(X, smem);

    gemm_mainloop<1, 8, OFFWS_AGG>(smem, sb, g_aW1T);

    if (tid < 64) g_a[blockIdx.x * 64 + tid] = sc[tid] + ab2[0];
}

// ---------------- kernel 3: softmax over 4096 paths ---------------------------
__global__ void k_soft() {
    __shared__ float red[1024];
    int t = threadIdx.x;
    float m = -1e30f;
    for (int i = t; i < NPATHS; i += 1024) m = fmaxf(m, g_a[i]);
    red[t] = m;
    __syncthreads();
    for (int s = 512; s > 0; s >>= 1) {
        if (t < s) red[t] = fmaxf(red[t], red[t + s]);
        __syncthreads();
    }
    float M = red[0];
    __syncthreads();
    float sum = 0.f;
    for (int i = t; i < NPATHS; i += 1024) sum += expf(g_a[i] - M);
    red[t] = sum;
    __syncthreads();
    for (int s = 512; s > 0; s >>= 1) {
        if (t < s) red[t] += red[t + s];
        __syncthreads();
    }
    float S = red[0];
    for (int i = t; i < NPATHS; i += 1024) g_aw[i] = expf(g_a[i] - M) / S;
}

// ---------------- kernel 4: partial weighted sums -----------------------------
__global__ void k_red() {
    int b = blockIdx.x, t = threadIdx.x;
    float a0 = 0.f, a1 = 0.f;
    for (int p = 0; p < 64; p++) {
        int pg = b * 64 + p;
        float w = g_aw[pg];
        const float* row = g_pf + (size_t)pg * 512;
        a0 = fmaf(w, row[t], a0);
        a1 = fmaf(w, row[t + 256], a1);
    }
    g_part[(size_t)b * 512 + t] = a0;
    g_part[(size_t)b * 512 + t + 256] = a1;
}

// ---------------- kernel 5: final reduction -----------------------------------
__global__ void k_fin(float* __restrict__ out) {
    int t = threadIdx.x;
    float s = 0.f;
    for (int b = 0; b < 64; b++) s += g_part[(size_t)b * 512 + t];
    out[t] = s;
}

// ---------------- entry -------------------------------------------------------
extern "C" void kernel_launch(void* const* d_in, const int* in_sizes, int n_in,
                              void* d_out, int out_size) {
    const float* nodes   = (const float*)d_in[0];
    const int*   lengths = (const int*)  d_in[1];
    const float* pW1     = (const float*)d_in[2];
    const float* pb1     = (const float*)d_in[3];
    const float* pw2     = (const float*)d_in[4];
    const float* pb2     = (const float*)d_in[5];
    const float* aW1     = (const float*)d_in[6];
    const float* ab1     = (const float*)d_in[7];
    const float* aw2     = (const float*)d_in[8];
    const float* ab2     = (const float*)d_in[9];
    float* out = (float*)d_out;

    cudaFuncSetAttribute(k_path, cudaFuncAttributeMaxDynamicSharedMemorySize, SMEM_PATH);
    cudaFuncSetAttribute(k_agg,  cudaFuncAttributeMaxDynamicSharedMemorySize, SMEM_AGG);

    __half* w1t;  cudaGetSymbolAddress((void**)&w1t,  g_W1T);
    __half* aw1t; cudaGetSymbolAddress((void**)&aw1t, g_aW1T);

    k_conv<<<dim3(8, 8), 256>>>(pW1, w1t);     // launch 0
    k_conv<<<dim3(8, 8), 256>>>(aW1, aw1t);    // launch 1
    k_path<<<NPATHS, 256, SMEM_PATH>>>(nodes, lengths, pb1, pw2, pb2);  // 2
    k_agg<<<NPATHS / 64, 256, SMEM_AGG>>>(ab1, aw2, ab2);               // 3
    k_soft<<<1, 1024>>>();
    k_red<<<64, 256>>>();
    k_fin<<<1, 512>>>(out);
}

// round 9
// speedup vs baseline: 1.5307x; 1.0311x over previous
#include <cuda_runtime.h>
#include <cuda_fp16.h>
#include <cstdint>
#include <cstddef>

// ============================================================================
// AttentionNetwork: P=4096, LMAX=64, D=512, H=512  (fp16 mma.sync path)
// R9: k_path single barrier per mainloop iteration (was 2); k_zero inserted
// at launch index 2 so ncu (which captures launch #3) finally profiles k_path.
// k_path: M=64/CTA, occ 2, warp tile 32x64, 2-buffer W ring of 256n x 32k.
// ============================================================================

#define NPATHS 4096

// ---------------- device scratch --------------------------------------------
__device__ __half g_W1T[512 * 512];   // pW1^T  [n][k]
__device__ __half g_aW1T[512 * 512];  // aW1^T  [n][k]
__device__ float g_pf[NPATHS * 512];  // paths_fea
__device__ float g_a[NPATHS];         // path logits
__device__ float g_aw[NPATHS];        // path softmax weights
__device__ float g_part[64 * 512];    // reduction partials

// ---------------- SMEM layout (bytes) ----------------------------------------
#define OFF_SC   0            // scores (<=128 floats)
#define OFF_WTS  512          // softmax weights
#define OFF_B1   1024         // 512 floats
#define OFF_W2   3072         // 512 floats
#define OFF_XS   5120         // X tile: ROWS x 1040B
#define XSTRIDE  1040
#define WSTRIDE  144          // k_agg W row stride

// k_path: X 64 rows (66560); W ring: 2 bufs x (256n x 32k, stride 80B)
#define OFFWS_P   71680                     // 5120 + 64*1040
#define WSTRIDE_P 80
#define WSBUF_P   20480                     // 256*80
#define SMEM_PATH (71680 + 2 * 20480)       // 112640 -> 2 CTAs/SM
// k_agg: 64 X rows, NP=8 (W chunk 256x64, buf 36864), 4 bufs
#define OFFWS_AGG 71680
#define SMEM_AGG  (71680 + 4 * 36864)       // 219136

// ---------------- PTX helpers ------------------------------------------------
__device__ __forceinline__ uint32_t smem_u32(const void* p) {
    uint32_t a;
    asm("{ .reg .u64 t; cvta.to.shared.u64 t, %1; cvt.u32.u64 %0, t; }"
        : "=r"(a) : "l"(p));
    return a;
}

__device__ __forceinline__ void ldsm4(uint32_t* r, uint32_t addr) {
    asm volatile("ldmatrix.sync.aligned.m8n8.x4.shared.b16 {%0,%1,%2,%3}, [%4];"
                 : "=r"(r[0]), "=r"(r[1]), "=r"(r[2]), "=r"(r[3]) : "r"(addr));
}

__device__ __forceinline__ void mma_f16(float* c, const uint32_t* a,
                                        uint32_t b0, uint32_t b1) {
    asm volatile(
        "mma.sync.aligned.m16n8k16.row.col.f32.f16.f16.f32 "
        "{%0,%1,%2,%3}, {%4,%5,%6,%7}, {%8,%9}, {%0,%1,%2,%3};"
        : "+f"(c[0]), "+f"(c[1]), "+f"(c[2]), "+f"(c[3])
        : "r"(a[0]), "r"(a[1]), "r"(a[2]), "r"(a[3]), "r"(b0), "r"(b1));
}

#define CP_ASYNC16(dst, src) \
    asm volatile("cp.async.cg.shared.global [%0], [%1], 16;" \
                 :: "r"(dst), "l"(src) : "memory")
#define CP_COMMIT() asm volatile("cp.async.commit_group;" ::: "memory")
#define CP_WAIT(n)  asm volatile("cp.async.wait_group %0;" :: "n"(n) : "memory")

// convert one float4 -> 8B (2x half2) and store to SMEM
__device__ __forceinline__ void sts_f16x4(char* smem, uint32_t off, float4 v) {
    __half2 p0, p1;
    p0.x = __float2half_rn(v.x); p0.y = __float2half_rn(v.y);
    p1.x = __float2half_rn(v.z); p1.y = __float2half_rn(v.w);
    uint2 st;
    st.x = *(uint32_t*)&p0;
    st.y = *(uint32_t*)&p1;
    *(uint2*)(smem + off) = st;
}

// ============================================================================
//                       k_path building blocks
// ============================================================================

// prefetch W chunk s (= nc*16 + kc): 256 n-rows x 32 k -> ring buf
__device__ __forceinline__ void prefetch_Wp(const __half* __restrict__ Wt,
                                            int s, int buf, uint32_t sb) {
    int tid = threadIdx.x;
    int nc = s >> 4, kc = s & 15;
    const __half* src = Wt + (size_t)(nc * 256) * 512 + kc * 32;
#pragma unroll
    for (int i = 0; i < 4; i++) {
        int idx = tid + i * 256;          // 0..1023 16B slots
        int nl = idx >> 2;                // 4 x 16B per row
        int q  = idx & 3;
        uint32_t dst = sb + OFFWS_P + buf * WSBUF_P + nl * WSTRIDE_P + q * 16;
        CP_ASYNC16(dst, src + (size_t)nl * 512 + q * 8);
    }
    CP_COMMIT();
}

// ============================================================================
//                       k_agg building blocks
// ============================================================================

template <int ROWS>
__device__ __forceinline__ void load_X_f16(const float* __restrict__ src,
                                           char* smem) {
    int tid = threadIdx.x;
#pragma unroll 4
    for (int i = 0; i < ROWS / 2; i++) {
        int idx = tid + i * 256;
        int m = idx >> 7;
        int q = idx & 127;
        float4 v = *(const float4*)(src + (size_t)m * 512 + q * 4);
        sts_f16x4(smem, OFF_XS + m * XSTRIDE + q * 8, v);
    }
}

template <int NP, int OFFWS>
__device__ __forceinline__ void prefetch_W(const __half* __restrict__ Wt,
                                           int s, int buf, uint32_t sb) {
    constexpr int WSBUF = NP * 32 * WSTRIDE;
    int tid = threadIdx.x;
    int nc = s >> 3, kc = s & 7;
    const __half* src = Wt + (size_t)(nc * NP * 32) * 512 + kc * 64;
#pragma unroll
    for (int i = 0; i < NP; i++) {
        int idx = tid + i * 256;
        int nl = idx >> 3;
        int q  = idx & 7;
        uint32_t dst = sb + OFFWS + buf * WSBUF + nl * WSTRIDE + q * 16;
        CP_ASYNC16(dst, src + (size_t)nl * 512 + q * 8);
    }
    CP_COMMIT();
}

// k_agg mainloop: warp tile 64x32
template <int MP, int NP, int OFFWS>
__device__ __forceinline__ void gemm_mainloop(char* smem, uint32_t sb,
                                              const __half* __restrict__ Wt) {
    constexpr int WSBUF = NP * 32 * WSTRIDE;
    constexpr int S = (512 / (NP * 32)) * 8;
    int tid = threadIdx.x;
    int lane = tid & 31, wid = tid >> 5;
    int m_part = (MP == 1) ? 0 : (wid & (MP - 1));
    int n_part = wid / MP;
    const float* b1s = (const float*)(smem + OFF_B1);
    const float* w2s = (const float*)(smem + OFF_W2);
    float* sc = (float*)(smem + OFF_SC);

    int lr = lane & 7;
    uint32_t aA[4];
#pragma unroll
    for (int mi = 0; mi < 4; mi++)
        aA[mi] = sb + OFF_XS +
                 (m_part * 64 + mi * 16 + ((lane >> 3) & 1) * 8 + lr) * XSTRIDE +
                 (lane >> 4) * 16;
    uint32_t bA[2];
#pragma unroll
    for (int nj = 0; nj < 2; nj++)
        bA[nj] = sb + OFFWS +
                 (n_part * 32 + nj * 16 + (lane >> 4) * 8 + lr) * WSTRIDE +
                 ((lane >> 3) & 1) * 16;

    float acc[4][4][4];
#pragma unroll
    for (int mi = 0; mi < 4; mi++)
#pragma unroll
        for (int nq = 0; nq < 4; nq++)
#pragma unroll
            for (int q = 0; q < 4; q++) acc[mi][nq][q] = 0.f;
    float rs[8];
#pragma unroll
    for (int i = 0; i < 8; i++) rs[i] = 0.f;

    for (int s = 0; s < S; s++) {
        __syncthreads();
        if (s + 3 < S) prefetch_W<NP, OFFWS>(Wt, s + 3, (s + 3) & 3, sb);
        else CP_COMMIT();
        CP_WAIT(3);
        __syncthreads();

        int kc = s & 7;
        uint32_t buf = (uint32_t)(s & 3) * WSBUF;
        uint32_t A[2][4][4], B[2][2][4];
        {
            uint32_t kx = kc * 128;
#pragma unroll
            for (int mi = 0; mi < 4; mi++) ldsm4(A[0][mi], aA[mi] + kx);
#pragma unroll
            for (int nj = 0; nj < 2; nj++) ldsm4(B[0][nj], bA[nj] + buf);
        }
#pragma unroll
        for (int k16 = 0; k16 < 4; k16++) {
            int cur = k16 & 1, nxt = cur ^ 1;
            if (k16 < 3) {
                uint32_t kxX = kc * 128 + (k16 + 1) * 32;
                uint32_t kxW = (k16 + 1) * 32;
#pragma unroll
                for (int mi = 0; mi < 4; mi++) ldsm4(A[nxt][mi], aA[mi] + kxX);
#pragma unroll
                for (int nj = 0; nj < 2; nj++) ldsm4(B[nxt][nj], bA[nj] + buf + kxW);
            }
#pragma unroll
            for (int mi = 0; mi < 4; mi++)
#pragma unroll
                for (int nj = 0; nj < 2; nj++) {
                    mma_f16(acc[mi][nj * 2],     A[cur][mi], B[cur][nj][0], B[cur][nj][1]);
                    mma_f16(acc[mi][nj * 2 + 1], A[cur][mi], B[cur][nj][2], B[cur][nj][3]);
                }
        }

        if ((s & 7) == 7) {
            int nc = s >> 3;
            int t2 = (lane & 3) * 2;
#pragma unroll
            for (int mi = 0; mi < 4; mi++)
#pragma unroll
                for (int nq = 0; nq < 4; nq++) {
                    int n0 = nc * (NP * 32) + n_part * 32 + nq * 8 + t2;
                    float bb0 = b1s[n0], bb1 = b1s[n0 + 1];
                    float ww0 = w2s[n0], ww1 = w2s[n0 + 1];
                    float* cc = acc[mi][nq];
                    rs[mi * 2 + 0] += fmaxf(cc[0] + bb0, 0.f) * ww0 +
                                      fmaxf(cc[1] + bb1, 0.f) * ww1;
                    rs[mi * 2 + 1] += fmaxf(cc[2] + bb0, 0.f) * ww0 +
                                      fmaxf(cc[3] + bb1, 0.f) * ww1;
                    cc[0] = cc[1] = cc[2] = cc[3] = 0.f;
                }
        }
    }

#pragma unroll
    for (int i = 0; i < 8; i++) {
        rs[i] += __shfl_xor_sync(0xffffffffu, rs[i], 1);
        rs[i] += __shfl_xor_sync(0xffffffffu, rs[i], 2);
    }
    if ((lane & 3) == 0) {
        int g = lane >> 2;
#pragma unroll
        for (int mi = 0; mi < 4; mi++) {
            atomicAdd(&sc[m_part * 64 + mi * 16 + g],     rs[mi * 2 + 0]);
            atomicAdd(&sc[m_part * 64 + mi * 16 + 8 + g], rs[mi * 2 + 1]);
        }
    }
    __syncthreads();
}

// ---------------- kernel 0: transpose + convert weights ----------------------
__global__ void k_conv(const float* __restrict__ src, __half* __restrict__ dst) {
    __shared__ float tile[64][65];
    int k0 = blockIdx.y * 64, n0 = blockIdx.x * 64;
    for (int i = threadIdx.x; i < 4096; i += 256) {
        int r = i >> 6, cth = i & 63;
        tile[r][cth] = src[(size_t)(k0 + r) * 512 + n0 + cth];
    }
    __syncthreads();
    for (int i = threadIdx.x; i < 4096; i += 256) {
        int r = i >> 6, cth = i & 63;
        dst[(size_t)(n0 + r) * 512 + k0 + cth] = __float2half_rn(tile[cth][r]);
    }
}

// ---------------- kernel 0b: tiny launch so k_path lands at ncu's slot -------
__global__ void k_zero() {
    g_a[blockIdx.x * 64 + threadIdx.x] = 0.f;   // overwritten later by k_agg
}

// ---------------- kernel 1: fused per-path stage (M=64, occ 2, 1 bar/iter) ----
__global__ void __launch_bounds__(256, 2)
k_path(const float* __restrict__ nodes, const int* __restrict__ lengths,
       const float* __restrict__ pb1, const float* __restrict__ pw2,
       const float* __restrict__ pb2) {
    extern __shared__ char smem[];
    uint32_t sb = smem_u32(smem);
    int tid = threadIdx.x;
    int lane = tid & 31, wid = tid >> 5;
    int m_part = wid & 1;                 // 32-row M slice
    int n_part = wid >> 1;                // 64-col slice of 256-N-chunk

    // chunk 0 starts streaming immediately; chunk 1 is issued at iter 0
    prefetch_Wp(g_W1T, 0, 0, sb);

    float* b1s = (float*)(smem + OFF_B1);
    float* w2s = (float*)(smem + OFF_W2);
    float* sc  = (float*)(smem + OFF_SC);
    for (int i = tid; i < 512; i += 256) { b1s[i] = pb1[i]; w2s[i] = pw2[i]; }
    if (tid < 64) sc[tid] = 0.f;

    // load X: 64 rows x 512 fp32 -> fp16 SMEM
    const float* X = nodes + (size_t)blockIdx.x * 64 * 512;
    load_X_f16<64>(X, smem);

    // per-lane ldmatrix bases
    int lr = lane & 7;
    uint32_t aA[2];
#pragma unroll
    for (int mi = 0; mi < 2; mi++)
        aA[mi] = sb + OFF_XS +
                 (m_part * 32 + mi * 16 + ((lane >> 3) & 1) * 8 + lr) * XSTRIDE +
                 (lane >> 4) * 16;
    uint32_t bA[4];
#pragma unroll
    for (int nj = 0; nj < 4; nj++)
        bA[nj] = sb + OFFWS_P +
                 (n_part * 64 + nj * 16 + (lane >> 4) * 8 + lr) * WSTRIDE_P +
                 ((lane >> 3) & 1) * 16;

    float acc[2][8][4];                   // 64 accumulator regs
#pragma unroll
    for (int mi = 0; mi < 2; mi++)
#pragma unroll
        for (int nq = 0; nq < 8; nq++)
#pragma unroll
            for (int q = 0; q < 4; q++) acc[mi][nq][q] = 0.f;
    float rs[4] = {0.f, 0.f, 0.f, 0.f};

    // mainloop: 32 iters = 2 N-chunks x 16 k-chunks (32 k each), ONE barrier
    for (int s = 0; s < 32; s++) {
        __syncthreads();                  // iter s-1 reads done (frees (s+1)&1)
                                          // also publishes X/sc/b1/w2 at s=0
        if (s + 1 < 32) prefetch_Wp(g_W1T, s + 1, (s + 1) & 1, sb);
        else CP_COMMIT();                 // keep group count aligned
        CP_WAIT(1);                       // chunk s landed (s+1 still pending)

        int kc = s & 15;
        uint32_t buf = (uint32_t)(s & 1) * WSBUF_P;
#pragma unroll
        for (int k16 = 0; k16 < 2; k16++) {
            uint32_t kxX = kc * 64 + k16 * 32;
            uint32_t kxW = k16 * 32;
            uint32_t A[2][4], B[4][4];
#pragma unroll
            for (int mi = 0; mi < 2; mi++) ldsm4(A[mi], aA[mi] + kxX);
#pragma unroll
            for (int nj = 0; nj < 4; nj++) ldsm4(B[nj], bA[nj] + buf + kxW);
#pragma unroll
            for (int mi = 0; mi < 2; mi++)
#pragma unroll
                for (int nj = 0; nj < 4; nj++) {
                    mma_f16(acc[mi][nj * 2],     A[mi], B[nj][0], B[nj][1]);
                    mma_f16(acc[mi][nj * 2 + 1], A[mi], B[nj][2], B[nj][3]);
                }
        }

        if (kc == 15) {
            // fold this 256-wide N chunk into per-row score partials
            int nc = s >> 4;
            int t2 = (lane & 3) * 2;
#pragma unroll
            for (int mi = 0; mi < 2; mi++)
#pragma unroll
                for (int nq = 0; nq < 8; nq++) {
                    int n0 = nc * 256 + n_part * 64 + nq * 8 + t2;
                    float bb0 = b1s[n0], bb1 = b1s[n0 + 1];
                    float ww0 = w2s[n0], ww1 = w2s[n0 + 1];
                    float* cc = acc[mi][nq];
                    rs[mi * 2 + 0] += fmaxf(cc[0] + bb0, 0.f) * ww0 +
                                      fmaxf(cc[1] + bb1, 0.f) * ww1;
                    rs[mi * 2 + 1] += fmaxf(cc[2] + bb0, 0.f) * ww0 +
                                      fmaxf(cc[3] + bb1, 0.f) * ww1;
                    cc[0] = cc[1] = cc[2] = cc[3] = 0.f;
                }
        }
    }

    // reduce the 4 lanes sharing each row, combine the 4 N-part warps
#pragma unroll
    for (int i = 0; i < 4; i++) {
        rs[i] += __shfl_xor_sync(0xffffffffu, rs[i], 1);
        rs[i] += __shfl_xor_sync(0xffffffffu, rs[i], 2);
    }
    if ((lane & 3) == 0) {
        int g = lane >> 2;
#pragma unroll
        for (int mi = 0; mi < 2; mi++) {
            atomicAdd(&sc[m_part * 32 + mi * 16 + g],     rs[mi * 2 + 0]);
            atomicAdd(&sc[m_part * 32 + mi * 16 + 8 + g], rs[mi * 2 + 1]);
        }
    }
    __syncthreads();

    // masked softmax over this path's 64 positions
    if (tid < 64) {
        int len = lengths[blockIdx.x];
        float mx = -1e30f;
        for (int j = 0; j < 64; j++) if (j < len) mx = fmaxf(mx, sc[j]);
        float sum = 0.f;
        for (int j = 0; j < 64; j++) if (j < len) sum += expf(sc[j] - mx);
        float w = (tid < len) ? expf(sc[tid] - mx) / sum : 0.f;
        ((float*)(smem + OFF_WTS))[tid] = w;
    }
    __syncthreads();

    // weighted sum of X rows (fp16 in SMEM) -> paths_fea
    const float* wts = (const float*)(smem + OFF_WTS);
    {
        int dp = tid;                     // fp16x2 column (0..255)
        float a0 = 0.f, a1 = 0.f;
        const char* base = smem + OFF_XS + dp * 4;
#pragma unroll 8
        for (int l = 0; l < 64; l++) {
            uint32_t v = *(const uint32_t*)(base + l * XSTRIDE);
            __half2 hv = *(__half2*)&v;
            float wl = wts[l];
            a0 = fmaf(wl, __half2float(hv.x), a0);
            a1 = fmaf(wl, __half2float(hv.y), a1);
        }
        float* dst = g_pf + (size_t)blockIdx.x * 512 + dp * 2;
        dst[0] = a0;
        dst[1] = a1;
    }
}

// ---------------- kernel 2: path-level MLP logits (M=64, grid 64) -------------
__global__ void __launch_bounds__(256, 1)
k_agg(const float* __restrict__ ab1, const float* __restrict__ aw2,
      const float* __restrict__ ab2) {
    extern __shared__ char smem[];
    uint32_t sb = smem_u32(smem);
    int tid = threadIdx.x;

    prefetch_W<8, OFFWS_AGG>(g_aW1T, 0, 0, sb);
    prefetch_W<8, OFFWS_AGG>(g_aW1T, 1, 1, sb);
    prefetch_W<8, OFFWS_AGG>(g_aW1T, 2, 2, sb);

    float* b1s = (float*)(smem + OFF_B1);
    float* w2s = (float*)(smem + OFF_W2);
    float* sc  = (float*)(smem + OFF_SC);
    for (int i = tid; i < 512; i += 256) { b1s[i] = ab1[i]; w2s[i] = aw2[i]; }
    if (tid < 64) sc[tid] = 0.f;

    const float* X = g_pf + (size_t)blockIdx.x * 64 * 512;
    load_X_f16<64>(X, smem);

    gemm_mainloop<1, 8, OFFWS_AGG>(smem, sb, g_aW1T);

    if (tid < 64) g_a[blockIdx.x * 64 + tid] = sc[tid] + ab2[0];
}

// ---------------- kernel 3: softmax over 4096 paths ---------------------------
__global__ void k_soft() {
    __shared__ float red[1024];
    int t = threadIdx.x;
    float m = -1e30f;
    for (int i = t; i < NPATHS; i += 1024) m = fmaxf(m, g_a[i]);
    red[t] = m;
    __syncthreads();
    for (int s = 512; s > 0; s >>= 1) {
        if (t < s) red[t] = fmaxf(red[t], red[t + s]);
        __syncthreads();
    }
    float M = red[0];
    __syncthreads();
    float sum = 0.f;
    for (int i = t; i < NPATHS; i += 1024) sum += expf(g_a[i] - M);
    red[t] = sum;
    __syncthreads();
    for (int s = 512; s > 0; s >>= 1) {
        if (t < s) red[t] += red[t + s];
        __syncthreads();
    }
    float S = red[0];
    for (int i = t; i < NPATHS; i += 1024) g_aw[i] = expf(g_a[i] - M) / S;
}

// ---------------- kernel 4: partial weighted sums -----------------------------
__global__ void k_red() {
    int b = blockIdx.x, t = threadIdx.x;
    float a0 = 0.f, a1 = 0.f;
    for (int p = 0; p < 64; p++) {
        int pg = b * 64 + p;
        float w = g_aw[pg];
        const float* row = g_pf + (size_t)pg * 512;
        a0 = fmaf(w, row[t], a0);
        a1 = fmaf(w, row[t + 256], a1);
    }
    g_part[(size_t)b * 512 + t] = a0;
    g_part[(size_t)b * 512 + t + 256] = a1;
}

// ---------------- kernel 5: final reduction -----------------------------------
__global__ void k_fin(float* __restrict__ out) {
    int t = threadIdx.x;
    float s = 0.f;
    for (int b = 0; b < 64; b++) s += g_part[(size_t)b * 512 + t];
    out[t] = s;
}

// ---------------- entry -------------------------------------------------------
extern "C" void kernel_launch(void* const* d_in, const int* in_sizes, int n_in,
                              void* d_out, int out_size) {
    const float* nodes   = (const float*)d_in[0];
    const int*   lengths = (const int*)  d_in[1];
    const float* pW1     = (const float*)d_in[2];
    const float* pb1     = (const float*)d_in[3];
    const float* pw2     = (const float*)d_in[4];
    const float* pb2     = (const float*)d_in[5];
    const float* aW1     = (const float*)d_in[6];
    const float* ab1     = (const float*)d_in[7];
    const float* aw2     = (const float*)d_in[8];
    const float* ab2     = (const float*)d_in[9];
    float* out = (float*)d_out;

    cudaFuncSetAttribute(k_path, cudaFuncAttributeMaxDynamicSharedMemorySize, SMEM_PATH);
    cudaFuncSetAttribute(k_agg,  cudaFuncAttributeMaxDynamicSharedMemorySize, SMEM_AGG);

    __half* w1t;  cudaGetSymbolAddress((void**)&w1t,  g_W1T);
    __half* aw1t; cudaGetSymbolAddress((void**)&aw1t, g_aW1T);

    k_conv<<<dim3(8, 8), 256>>>(pW1, w1t);     // idx 0
    k_conv<<<dim3(8, 8), 256>>>(aW1, aw1t);    // idx 1
    k_zero<<<64, 64>>>();                      // idx 2 (shifts ncu slot)
    k_path<<<NPATHS, 256, SMEM_PATH>>>(nodes, lengths, pb1, pw2, pb2);  // idx 3
    k_agg<<<NPATHS / 64, 256, SMEM_AGG>>>(ab1, aw2, ab2);               // idx 4
    k_soft<<<1, 1024>>>();
    k_red<<<64, 256>>>();
    k_fin<<<1, 512>>>(out);
}

// round 10
// speedup vs baseline: 1.5745x; 1.0286x over previous
#include <cuda_runtime.h>
#include <cuda_fp16.h>
#include <cstdint>
#include <cstddef>

// ============================================================================
// AttentionNetwork: P=4096, LMAX=64, D=512, H=512  (fp16 mma.sync path)
// R10: NO CTA barrier in the k_path mainloop. Warp-pairs (same B slice) use
// pair-private cp.async ring buffers (4 slots x 2KB) + 64-thread named
// barriers; pairs drift independently -> latency hiding without convoys.
// X tile stored unpadded with XOR swizzle (64KB) to keep SMEM at 103KB, occ 2.
// ============================================================================

#define NPATHS 4096

// ---------------- device scratch --------------------------------------------
__device__ __half g_W1T[512 * 512];   // pW1^T  [n][k]
__device__ __half g_aW1T[512 * 512];  // aW1^T  [n][k]
__device__ float g_pf[NPATHS * 512];  // paths_fea
__device__ float g_a[NPATHS];         // path logits
__device__ float g_aw[NPATHS];        // path softmax weights
__device__ float g_part[64 * 512];    // reduction partials

// ---------------- k_path SMEM layout (bytes) ----------------------------------
#define OFF_SC   0            // 64 floats
#define OFF_WTS  256          // 64 floats
#define OFF_B1   512          // 512 floats
#define OFF_W2   2560         // 512 floats
#define OFF_XS   4608         // X tile: 64 rows x 1024B, XOR-swizzled
#define OFF_WR   70144        // 4 pairs x 4 slots x 2048B = 32768
#define SMEM_PATH 102912      // -> 2 CTAs/SM

// ---------------- k_agg SMEM layout (R6, unchanged) ---------------------------
#define AG_SC    0
#define AG_B1    1024
#define AG_W2    3072
#define AG_XS    5120         // 64 rows x 1040B
#define AG_XSTR  1040
#define AG_WSTR  144
#define OFFWS_AGG 71680
#define SMEM_AGG  (71680 + 4 * 36864)   // 219136

// ---------------- PTX helpers ------------------------------------------------
__device__ __forceinline__ uint32_t smem_u32(const void* p) {
    uint32_t a;
    asm("{ .reg .u64 t; cvta.to.shared.u64 t, %1; cvt.u32.u64 %0, t; }"
        : "=r"(a) : "l"(p));
    return a;
}

__device__ __forceinline__ void ldsm4(uint32_t* r, uint32_t addr) {
    asm volatile("ldmatrix.sync.aligned.m8n8.x4.shared.b16 {%0,%1,%2,%3}, [%4];"
                 : "=r"(r[0]), "=r"(r[1]), "=r"(r[2]), "=r"(r[3]) : "r"(addr));
}

__device__ __forceinline__ void mma_f16(float* c, const uint32_t* a,
                                        uint32_t b0, uint32_t b1) {
    asm volatile(
        "mma.sync.aligned.m16n8k16.row.col.f32.f16.f16.f32 "
        "{%0,%1,%2,%3}, {%4,%5,%6,%7}, {%8,%9}, {%0,%1,%2,%3};"
        : "+f"(c[0]), "+f"(c[1]), "+f"(c[2]), "+f"(c[3])
        : "r"(a[0]), "r"(a[1]), "r"(a[2]), "r"(a[3]), "r"(b0), "r"(b1));
}

#define CP_ASYNC16(dst, src) \
    asm volatile("cp.async.cg.shared.global [%0], [%1], 16;" \
                 :: "r"(dst), "l"(src) : "memory")
#define CP_COMMIT() asm volatile("cp.async.commit_group;" ::: "memory")
#define CP_WAIT(n)  asm volatile("cp.async.wait_group %0;" :: "n"(n) : "memory")
#define BAR_SYNC(id, cnt) \
    asm volatile("bar.sync %0, %1;" :: "r"(id), "r"(cnt) : "memory")

// convert one float4 -> 8B (2x half2) and store to SMEM
__device__ __forceinline__ void sts_f16x4(char* smem, uint32_t off, float4 v) {
    __half2 p0, p1;
    p0.x = __float2half_rn(v.x); p0.y = __float2half_rn(v.y);
    p1.x = __float2half_rn(v.z); p1.y = __float2half_rn(v.w);
    uint2 st;
    st.x = *(uint32_t*)&p0;
    st.y = *(uint32_t*)&p1;
    *(uint2*)(smem + off) = st;
}

// ============================================================================
//                       k_path (R10)
// ============================================================================

// prefetch this warp's half of W chunk s (= nc*32 + kc): rows
// [nc*256 + pair*64 + half*32, +32), k halfs [kc*16, +16) -> pair slot.
__device__ __forceinline__ void prefetch_Wpair(const __half* __restrict__ Wt,
                                               int s, uint32_t slotbase,
                                               int pair, int half, int lane) {
    int nc = s >> 5, kc = s & 31;
    int nbase = nc * 256 + pair * 64 + half * 32;
    const __half* src = Wt + (size_t)nbase * 512 + kc * 16;
#pragma unroll
    for (int i = 0; i < 2; i++) {
        int idx = lane + i * 32;          // 0..63
        int nl = half * 32 + (idx >> 1);  // row in 64-row chunk
        int q  = (idx & 1) << 4;          // 0 or 16 bytes
        uint32_t dst = slotbase + nl * 32 + (q ^ (((nl >> 2) & 1) << 4));
        CP_ASYNC16(dst, src + (size_t)(idx >> 1) * 512 + (q >> 1));
    }
    CP_COMMIT();
}

__global__ void __launch_bounds__(256, 2)
k_path(const float* __restrict__ nodes, const int* __restrict__ lengths,
       const float* __restrict__ pb1, const float* __restrict__ pw2,
       const float* __restrict__ pb2) {
    extern __shared__ char smem[];
    uint32_t sb = smem_u32(smem);
    int tid = threadIdx.x;
    int lane = tid & 31, wid = tid >> 5;
    int m_part = wid & 1;                 // 32-row M slice (also W-half owner)
    int pair   = wid >> 1;                // 0..3 : 64-col slice of 256-N-chunk
    uint32_t pairBase = sb + OFF_WR + pair * (4 * 2048);

    // start this warp's W stream immediately (chunks 0,1,2)
    prefetch_Wpair(g_W1T, 0, pairBase + 0 * 2048, pair, m_part, lane);
    prefetch_Wpair(g_W1T, 1, pairBase + 1 * 2048, pair, m_part, lane);
    prefetch_Wpair(g_W1T, 2, pairBase + 2 * 2048, pair, m_part, lane);

    float* b1s = (float*)(smem + OFF_B1);
    float* w2s = (float*)(smem + OFF_W2);
    float* sc  = (float*)(smem + OFF_SC);
    for (int i = tid; i < 512; i += 256) { b1s[i] = pb1[i]; w2s[i] = pw2[i]; }
    if (tid < 64) sc[tid] = 0.f;

    // load X: 64 rows x 512 fp32 -> fp16, XOR-swizzled, stride 1024B
    const float* X = nodes + (size_t)blockIdx.x * 64 * 512;
#pragma unroll 4
    for (int i = 0; i < 32; i++) {
        int idx = tid + i * 256;          // 0..8191 float4 slots
        int m = idx >> 7;                 // 128 float4 per row
        int q = idx & 127;
        float4 v = *(const float4*)(X + (size_t)m * 512 + q * 4);
        uint32_t c = (uint32_t)(q * 8);
        uint32_t off = OFF_XS + m * 1024 + (c ^ (((uint32_t)(m & 7)) << 4));
        sts_f16x4(smem, off, v);
    }
    __syncthreads();                      // publish X + sc + b1/w2

    // per-lane ldmatrix bases
    int lr = lane & 7;
    uint32_t aswz = (uint32_t)lr << 4;                 // X swizzle mask
    uint32_t a16  = (uint32_t)((lane >> 4) & 1) << 4;  // k 16B-half select
    uint32_t aRow[2];
#pragma unroll
    for (int mi = 0; mi < 2; mi++)
        aRow[mi] = sb + OFF_XS +
                   (m_part * 32 + mi * 16 + ((lane >> 3) & 1) * 8 + lr) * 1024;
    // B bases within a slot (add slotoff per iter); swizzle is lane-constant
    uint32_t bB[4];
#pragma unroll
    for (int nj = 0; nj < 4; nj++) {
        int row = nj * 16 + ((lane >> 4) & 1) * 8 + lr;
        uint32_t csel = (uint32_t)((lane >> 3) & 1) << 4;
        uint32_t bswz = (uint32_t)((lr >> 2) & 1) << 4;
        bB[nj] = pairBase + row * 32 + (csel ^ bswz);
    }

    float acc[2][8][4];                   // 64 accumulator regs
#pragma unroll
    for (int mi = 0; mi < 2; mi++)
#pragma unroll
        for (int nq = 0; nq < 8; nq++)
#pragma unroll
            for (int q = 0; q < 4; q++) acc[mi][nq][q] = 0.f;
    float rs[4] = {0.f, 0.f, 0.f, 0.f};

    int barid = 1 + pair;

    // mainloop: 64 iters = 2 N-chunks x 32 k16-chunks. NO CTA barrier.
    for (int s = 0; s < 64; s++) {
        BAR_SYNC(barid, 64);              // pair rendezvous: slot (s-1) free,
                                          // partner's chunk-s half committed
        if (s + 3 < 64)
            prefetch_Wpair(g_W1T, s + 3, pairBase + ((s + 3) & 3) * 2048,
                           pair, m_part, lane);
        else
            CP_COMMIT();                  // keep group count aligned
        CP_WAIT(3);                       // own half of chunk s landed;
        BAR_SYNC(barid, 64);              // partner's half landed too

        int kc = s & 31;
        uint32_t slotoff = (uint32_t)(s & 3) * 2048;
        uint32_t kb = (uint32_t)kc * 32;
        uint32_t A[2][4], B[4][4];
#pragma unroll
        for (int mi = 0; mi < 2; mi++)
            ldsm4(A[mi], aRow[mi] + ((kb | a16) ^ aswz));
#pragma unroll
        for (int nj = 0; nj < 4; nj++)
            ldsm4(B[nj], bB[nj] + slotoff);
#pragma unroll
        for (int mi = 0; mi < 2; mi++)
#pragma unroll
            for (int nj = 0; nj < 4; nj++) {
                mma_f16(acc[mi][nj * 2],     A[mi], B[nj][0], B[nj][1]);
                mma_f16(acc[mi][nj * 2 + 1], A[mi], B[nj][2], B[nj][3]);
            }

        if (kc == 31) {
            // fold this 256-wide N chunk into per-row score partials
            int nc = s >> 5;
            int t2 = (lane & 3) * 2;
#pragma unroll
            for (int mi = 0; mi < 2; mi++)
#pragma unroll
                for (int nq = 0; nq < 8; nq++) {
                    int n0 = nc * 256 + pair * 64 + nq * 8 + t2;
                    float bb0 = b1s[n0], bb1 = b1s[n0 + 1];
                    float ww0 = w2s[n0], ww1 = w2s[n0 + 1];
                    float* cc = acc[mi][nq];
                    rs[mi * 2 + 0] += fmaxf(cc[0] + bb0, 0.f) * ww0 +
                                      fmaxf(cc[1] + bb1, 0.f) * ww1;
                    rs[mi * 2 + 1] += fmaxf(cc[2] + bb0, 0.f) * ww0 +
                                      fmaxf(cc[3] + bb1, 0.f) * ww1;
                    cc[0] = cc[1] = cc[2] = cc[3] = 0.f;
                }
        }
    }

    // reduce the 4 lanes sharing each row, combine the 4 pair warps
#pragma unroll
    for (int i = 0; i < 4; i++) {
        rs[i] += __shfl_xor_sync(0xffffffffu, rs[i], 1);
        rs[i] += __shfl_xor_sync(0xffffffffu, rs[i], 2);
    }
    if ((lane & 3) == 0) {
        int g = lane >> 2;
#pragma unroll
        for (int mi = 0; mi < 2; mi++) {
            atomicAdd(&sc[m_part * 32 + mi * 16 + g],     rs[mi * 2 + 0]);
            atomicAdd(&sc[m_part * 32 + mi * 16 + 8 + g], rs[mi * 2 + 1]);
        }
    }
    __syncthreads();

    // masked softmax over this path's 64 positions
    if (tid < 64) {
        int len = lengths[blockIdx.x];
        float mx = -1e30f;
        for (int j = 0; j < 64; j++) if (j < len) mx = fmaxf(mx, sc[j]);
        float sum = 0.f;
        for (int j = 0; j < 64; j++) if (j < len) sum += expf(sc[j] - mx);
        float w = (tid < len) ? expf(sc[tid] - mx) / sum : 0.f;
        ((float*)(smem + OFF_WTS))[tid] = w;
    }
    __syncthreads();

    // weighted sum of X rows (fp16, swizzled) -> paths_fea
    const float* wts = (const float*)(smem + OFF_WTS);
    {
        int dp = tid;                     // fp16x2 column (0..255)
        float a0 = 0.f, a1 = 0.f;
        uint32_t cbyte = (uint32_t)dp * 4;
#pragma unroll 8
        for (int l = 0; l < 64; l++) {
            uint32_t off = OFF_XS + l * 1024 +
                           (cbyte ^ (((uint32_t)(l & 7)) << 4));
            uint32_t v = *(const uint32_t*)(smem + off);
            __half2 hv = *(__half2*)&v;
            float wl = wts[l];
            a0 = fmaf(wl, __half2float(hv.x), a0);
            a1 = fmaf(wl, __half2float(hv.y), a1);
        }
        float* dst = g_pf + (size_t)blockIdx.x * 512 + dp * 2;
        dst[0] = a0;
        dst[1] = a1;
    }
}

// ============================================================================
//                       k_agg (R6 structure, unchanged)
// ============================================================================

__device__ __forceinline__ void ag_prefetch(const __half* __restrict__ Wt,
                                            int s, int buf, uint32_t sb) {
    int tid = threadIdx.x;
    int nc = s >> 3, kc = s & 7;
    const __half* src = Wt + (size_t)(nc * 256) * 512 + kc * 64;
#pragma unroll
    for (int i = 0; i < 8; i++) {
        int idx = tid + i * 256;
        int nl = idx >> 3;
        int q  = idx & 7;
        uint32_t dst = sb + OFFWS_AGG + buf * 36864 + nl * AG_WSTR + q * 16;
        CP_ASYNC16(dst, src + (size_t)nl * 512 + q * 8);
    }
    CP_COMMIT();
}

__global__ void __launch_bounds__(256, 1)
k_agg(const float* __restrict__ ab1, const float* __restrict__ aw2,
      const float* __restrict__ ab2) {
    extern __shared__ char smem[];
    uint32_t sb = smem_u32(smem);
    int tid = threadIdx.x;
    int lane = tid & 31, wid = tid >> 5;
    int n_part = wid;                     // 32-col slice of 256-N-chunk

    ag_prefetch(g_aW1T, 0, 0, sb);
    ag_prefetch(g_aW1T, 1, 1, sb);
    ag_prefetch(g_aW1T, 2, 2, sb);

    float* b1s = (float*)(smem + AG_B1);
    float* w2s = (float*)(smem + AG_W2);
    float* sc  = (float*)(smem + AG_SC);
    for (int i = tid; i < 512; i += 256) { b1s[i] = ab1[i]; w2s[i] = aw2[i]; }
    if (tid < 64) sc[tid] = 0.f;

    const float* X = g_pf + (size_t)blockIdx.x * 64 * 512;
#pragma unroll 4
    for (int i = 0; i < 32; i++) {
        int idx = tid + i * 256;
        int m = idx >> 7;
        int q = idx & 127;
        float4 v = *(const float4*)(X + (size_t)m * 512 + q * 4);
        sts_f16x4(smem, AG_XS + m * AG_XSTR + q * 8, v);
    }

    int lr = lane & 7;
    uint32_t aA[4];
#pragma unroll
    for (int mi = 0; mi < 4; mi++)
        aA[mi] = sb + AG_XS +
                 (mi * 16 + ((lane >> 3) & 1) * 8 + lr) * AG_XSTR +
                 (lane >> 4) * 16;
    uint32_t bA[2];
#pragma unroll
    for (int nj = 0; nj < 2; nj++)
        bA[nj] = sb + OFFWS_AGG +
                 (n_part * 32 + nj * 16 + (lane >> 4) * 8 + lr) * AG_WSTR +
                 ((lane >> 3) & 1) * 16;

    float acc[4][4][4];
#pragma unroll
    for (int mi = 0; mi < 4; mi++)
#pragma unroll
        for (int nq = 0; nq < 4; nq++)
#pragma unroll
            for (int q = 0; q < 4; q++) acc[mi][nq][q] = 0.f;
    float rs[8];
#pragma unroll
    for (int i = 0; i < 8; i++) rs[i] = 0.f;

    for (int s = 0; s < 16; s++) {
        __syncthreads();
        if (s + 3 < 16) ag_prefetch(g_aW1T, s + 3, (s + 3) & 3, sb);
        else CP_COMMIT();
        CP_WAIT(3);
        __syncthreads();

        int kc = s & 7;
        uint32_t buf = (uint32_t)(s & 3) * 36864;
#pragma unroll
        for (int k16 = 0; k16 < 4; k16++) {
            uint32_t kxX = kc * 128 + k16 * 32;
            uint32_t kxW = k16 * 32;
            uint32_t A[4][4], B[2][4];
#pragma unroll
            for (int mi = 0; mi < 4; mi++) ldsm4(A[mi], aA[mi] + kxX);
#pragma unroll
            for (int nj = 0; nj < 2; nj++) ldsm4(B[nj], bA[nj] + buf + kxW);
#pragma unroll
            for (int mi = 0; mi < 4; mi++)
#pragma unroll
                for (int nj = 0; nj < 2; nj++) {
                    mma_f16(acc[mi][nj * 2],     A[mi], B[nj][0], B[nj][1]);
                    mma_f16(acc[mi][nj * 2 + 1], A[mi], B[nj][2], B[nj][3]);
                }
        }

        if ((s & 7) == 7) {
            int nc = s >> 3;
            int t2 = (lane & 3) * 2;
#pragma unroll
            for (int mi = 0; mi < 4; mi++)
#pragma unroll
                for (int nq = 0; nq < 4; nq++) {
                    int n0 = nc * 256 + n_part * 32 + nq * 8 + t2;
                    float bb0 = b1s[n0], bb1 = b1s[n0 + 1];
                    float ww0 = w2s[n0], ww1 = w2s[n0 + 1];
                    float* cc = acc[mi][nq];
                    rs[mi * 2 + 0] += fmaxf(cc[0] + bb0, 0.f) * ww0 +
                                      fmaxf(cc[1] + bb1, 0.f) * ww1;
                    rs[mi * 2 + 1] += fmaxf(cc[2] + bb0, 0.f) * ww0 +
                                      fmaxf(cc[3] + bb1, 0.f) * ww1;
                    cc[0] = cc[1] = cc[2] = cc[3] = 0.f;
                }
        }
    }

#pragma unroll
    for (int i = 0; i < 8; i++) {
        rs[i] += __shfl_xor_sync(0xffffffffu, rs[i], 1);
        rs[i] += __shfl_xor_sync(0xffffffffu, rs[i], 2);
    }
    if ((lane & 3) == 0) {
        int g = lane >> 2;
#pragma unroll
        for (int mi = 0; mi < 4; mi++) {
            atomicAdd(&sc[mi * 16 + g],     rs[mi * 2 + 0]);
            atomicAdd(&sc[mi * 16 + 8 + g], rs[mi * 2 + 1]);
        }
    }
    __syncthreads();

    if (tid < 64) g_a[blockIdx.x * 64 + tid] = sc[tid] + ab2[0];
}

// ---------------- kernel 0: transpose + convert weights ----------------------
__global__ void k_conv(const float* __restrict__ src, __half* __restrict__ dst) {
    __shared__ float tile[64][65];
    int k0 = blockIdx.y * 64, n0 = blockIdx.x * 64;
    for (int i = threadIdx.x; i < 4096; i += 256) {
        int r = i >> 6, cth = i & 63;
        tile[r][cth] = src[(size_t)(k0 + r) * 512 + n0 + cth];
    }
    __syncthreads();
    for (int i = threadIdx.x; i < 4096; i += 256) {
        int r = i >> 6, cth = i & 63;
        dst[(size_t)(n0 + r) * 512 + k0 + cth] = __float2half_rn(tile[cth][r]);
    }
}

// ---------------- kernel 0b: keeps k_path at ncu's capture slot ---------------
__global__ void k_zero() {
    g_a[blockIdx.x * 64 + threadIdx.x] = 0.f;   // overwritten later by k_agg
}

// ---------------- kernel 3: softmax over 4096 paths ---------------------------
__global__ void k_soft() {
    __shared__ float red[1024];
    int t = threadIdx.x;
    float m = -1e30f;
    for (int i = t; i < NPATHS; i += 1024) m = fmaxf(m, g_a[i]);
    red[t] = m;
    __syncthreads();
    for (int s = 512; s > 0; s >>= 1) {
        if (t < s) red[t] = fmaxf(red[t], red[t + s]);
        __syncthreads();
    }
    float M = red[0];
    __syncthreads();
    float sum = 0.f;
    for (int i = t; i < NPATHS; i += 1024) sum += expf(g_a[i] - M);
    red[t] = sum;
    __syncthreads();
    for (int s = 512; s > 0; s >>= 1) {
        if (t < s) red[t] += red[t + s];
        __syncthreads();
    }
    float S = red[0];
    for (int i = t; i < NPATHS; i += 1024) g_aw[i] = expf(g_a[i] - M) / S;
}

// ---------------- kernel 4: partial weighted sums -----------------------------
__global__ void k_red() {
    int b = blockIdx.x, t = threadIdx.x;
    float a0 = 0.f, a1 = 0.f;
    for (int p = 0; p < 64; p++) {
        int pg = b * 64 + p;
        float w = g_aw[pg];
        const float* row = g_pf + (size_t)pg * 512;
        a0 = fmaf(w, row[t], a0);
        a1 = fmaf(w, row[t + 256], a1);
    }
    g_part[(size_t)b * 512 + t] = a0;
    g_part[(size_t)b * 512 + t + 256] = a1;
}

// ---------------- kernel 5: final reduction -----------------------------------
__global__ void k_fin(float* __restrict__ out) {
    int t = threadIdx.x;
    float s = 0.f;
    for (int b = 0; b < 64; b++) s += g_part[(size_t)b * 512 + t];
    out[t] = s;
}

// ---------------- entry -------------------------------------------------------
extern "C" void kernel_launch(void* const* d_in, const int* in_sizes, int n_in,
                              void* d_out, int out_size) {
    const float* nodes   = (const float*)d_in[0];
    const int*   lengths = (const int*)  d_in[1];
    const float* pW1     = (const float*)d_in[2];
    const float* pb1     = (const float*)d_in[3];
    const float* pw2     = (const float*)d_in[4];
    const float* pb2     = (const float*)d_in[5];
    const float* aW1     = (const float*)d_in[6];
    const float* ab1     = (const float*)d_in[7];
    const float* aw2     = (const float*)d_in[8];
    const float* ab2     = (const float*)d_in[9];
    float* out = (float*)d_out;
    (void)pb2;

    cudaFuncSetAttribute(k_path, cudaFuncAttributeMaxDynamicSharedMemorySize, SMEM_PATH);
    cudaFuncSetAttribute(k_agg,  cudaFuncAttributeMaxDynamicSharedMemorySize, SMEM_AGG);

    __half* w1t;  cudaGetSymbolAddress((void**)&w1t,  g_W1T);
    __half* aw1t; cudaGetSymbolAddress((void**)&aw1t, g_aW1T);

    k_conv<<<dim3(8, 8), 256>>>(pW1, w1t);     // idx 0
    k_conv<<<dim3(8, 8), 256>>>(aW1, aw1t);    // idx 1
    k_zero<<<64, 64>>>();                      // idx 2 (ncu slot shift)
    k_path<<<NPATHS, 256, SMEM_PATH>>>(nodes, lengths, pb1, pw2, pb2);  // idx 3
    k_agg<<<NPATHS / 64, 256, SMEM_AGG>>>(ab1, aw2, ab2);               // idx 4
    k_soft<<<1, 1024>>>();
    k_red<<<64, 256>>>();
    k_fin<<<1, 512>>>(out);
}

// round 11
// speedup vs baseline: 1.7357x; 1.1024x over previous
#include <cuda_runtime.h>
#include <cuda_fp16.h>
#include <cstdint>
#include <cstddef>

// ============================================================================
// AttentionNetwork: P=4096, LMAX=64, D=512, H=512  (fp16 mma.sync path)
// R11: k_path k32 macro-iterations (16 MMAs per barrier-pair, 6-slot ring,
// distance-2 prefetch), b1/w2 via __ldg in folds, sc/wts overlaid on the dead
// ring. k_agg split over N (grid 128, atomicAdd partial scores into g_a).
// ============================================================================

#define NPATHS 4096

// ---------------- device scratch --------------------------------------------
__device__ __half g_W1T[512 * 512];   // pW1^T  [n][k]
__device__ __half g_aW1T[512 * 512];  // aW1^T  [n][k]
__device__ float g_pf[NPATHS * 512];  // paths_fea
__device__ float g_a[NPATHS];         // path logits (accumulated)
__device__ float g_aw[NPATHS];        // path softmax weights
__device__ float g_part[64 * 512];    // reduction partials

// ---------------- k_path SMEM layout (bytes) ----------------------------------
#define OFF_XS   0            // X tile: 64 rows x 1024B, XOR-swizzled
#define OFF_WR   65536        // 4 pairs x 6 slots x 2048B = 49152
#define OFF_SC   65536        // overlays ring after mainloop (64 floats)
#define OFF_WTS  65792        // overlays ring (64 floats)
#define SMEM_PATH 114688      // 112KB -> 2 CTAs/SM (2x(112K+1K) < 228K)

// ---------------- k_agg SMEM layout ------------------------------------------
#define AG_SC    0
#define AG_B1    1024
#define AG_W2    3072
#define AG_XS    5120         // 64 rows x 1040B
#define AG_XSTR  1040
#define AG_WSTR  144
#define OFFWS_AGG 71680
#define SMEM_AGG  (71680 + 4 * 36864)   // 219136

// ---------------- PTX helpers ------------------------------------------------
__device__ __forceinline__ uint32_t smem_u32(const void* p) {
    uint32_t a;
    asm("{ .reg .u64 t; cvta.to.shared.u64 t, %1; cvt.u32.u64 %0, t; }"
        : "=r"(a) : "l"(p));
    return a;
}

__device__ __forceinline__ void ldsm4(uint32_t* r, uint32_t addr) {
    asm volatile("ldmatrix.sync.aligned.m8n8.x4.shared.b16 {%0,%1,%2,%3}, [%4];"
                 : "=r"(r[0]), "=r"(r[1]), "=r"(r[2]), "=r"(r[3]) : "r"(addr));
}

__device__ __forceinline__ void mma_f16(float* c, const uint32_t* a,
                                        uint32_t b0, uint32_t b1) {
    asm volatile(
        "mma.sync.aligned.m16n8k16.row.col.f32.f16.f16.f32 "
        "{%0,%1,%2,%3}, {%4,%5,%6,%7}, {%8,%9}, {%0,%1,%2,%3};"
        : "+f"(c[0]), "+f"(c[1]), "+f"(c[2]), "+f"(c[3])
        : "r"(a[0]), "r"(a[1]), "r"(a[2]), "r"(a[3]), "r"(b0), "r"(b1));
}

#define CP_ASYNC16(dst, src) \
    asm volatile("cp.async.cg.shared.global [%0], [%1], 16;" \
                 :: "r"(dst), "l"(src) : "memory")
#define CP_COMMIT() asm volatile("cp.async.commit_group;" ::: "memory")
#define CP_WAIT(n)  asm volatile("cp.async.wait_group %0;" :: "n"(n) : "memory")
#define BAR_SYNC(id, cnt) \
    asm volatile("bar.sync %0, %1;" :: "r"(id), "r"(cnt) : "memory")

// convert one float4 -> 8B (2x half2) and store to SMEM
__device__ __forceinline__ void sts_f16x4(char* smem, uint32_t off, float4 v) {
    __half2 p0, p1;
    p0.x = __float2half_rn(v.x); p0.y = __float2half_rn(v.y);
    p1.x = __float2half_rn(v.z); p1.y = __float2half_rn(v.w);
    uint2 st;
    st.x = *(uint32_t*)&p0;
    st.y = *(uint32_t*)&p1;
    *(uint2*)(smem + off) = st;
}

// ============================================================================
//                       k_path (R11)
// ============================================================================

// prefetch this warp's halves of W group g (chunks 2g, 2g+1). chunk c:
// rows [nc*256 + pair*64 + half*32, +32), k [kc*16, +16) -> slot c%6.
__device__ __forceinline__ void prefetch_grp(const __half* __restrict__ Wt,
                                             int g, uint32_t pairBase,
                                             int pair, int half, int lane) {
#pragma unroll
    for (int c2 = 0; c2 < 2; c2++) {
        int c = 2 * g + c2;
        int nc = c >> 5, kc = c & 31;
        uint32_t slotbase = pairBase + (uint32_t)(c % 6) * 2048;
        const __half* src =
            Wt + (size_t)(nc * 256 + pair * 64 + half * 32) * 512 + kc * 16;
#pragma unroll
        for (int i = 0; i < 2; i++) {
            int idx = lane + i * 32;      // 0..63
            int nl = half * 32 + (idx >> 1);
            int q  = (idx & 1) << 4;
            uint32_t dst = slotbase + nl * 32 + (q ^ (((nl >> 2) & 1) << 4));
            CP_ASYNC16(dst, src + (size_t)(idx >> 1) * 512 + (q >> 1));
        }
    }
    CP_COMMIT();
}

__global__ void __launch_bounds__(256, 2)
k_path(const float* __restrict__ nodes, const int* __restrict__ lengths,
       const float* __restrict__ pb1, const float* __restrict__ pw2,
       const float* __restrict__ pb2) {
    extern __shared__ char smem[];
    uint32_t sb = smem_u32(smem);
    int tid = threadIdx.x;
    int lane = tid & 31, wid = tid >> 5;
    int m_part = wid & 1;                 // 32-row M slice (also W-half owner)
    int pair   = wid >> 1;                // 0..3 : 64-col slice of 256-N-chunk
    uint32_t pairBase = sb + OFF_WR + pair * (6 * 2048);

    // start this warp's W stream (groups 0,1 = chunks 0..3)
    prefetch_grp(g_W1T, 0, pairBase, pair, m_part, lane);
    prefetch_grp(g_W1T, 1, pairBase, pair, m_part, lane);

    // load X: 64 rows x 512 fp32 -> fp16, XOR-swizzled, stride 1024B
    const float* X = nodes + (size_t)blockIdx.x * 64 * 512;
#pragma unroll 4
    for (int i = 0; i < 32; i++) {
        int idx = tid + i * 256;          // 0..8191 float4 slots
        int m = idx >> 7;                 // 128 float4 per row
        int q = idx & 127;
        float4 v = *(const float4*)(X + (size_t)m * 512 + q * 4);
        uint32_t c = (uint32_t)(q * 8);
        uint32_t off = OFF_XS + m * 1024 + (c ^ (((uint32_t)(m & 7)) << 4));
        sts_f16x4(smem, off, v);
    }
    __syncthreads();                      // publish X

    // per-lane ldmatrix bases
    int lr = lane & 7;
    uint32_t aswz = (uint32_t)lr << 4;                 // X swizzle mask
    uint32_t a16  = (uint32_t)((lane >> 4) & 1) << 4;  // k 16B-half select
    uint32_t aRow[2];
#pragma unroll
    for (int mi = 0; mi < 2; mi++)
        aRow[mi] = sb + OFF_XS +
                   (m_part * 32 + mi * 16 + ((lane >> 3) & 1) * 8 + lr) * 1024;
    uint32_t bB[4];
#pragma unroll
    for (int nj = 0; nj < 4; nj++) {
        int row = nj * 16 + ((lane >> 4) & 1) * 8 + lr;
        uint32_t csel = (uint32_t)((lane >> 3) & 1) << 4;
        uint32_t bswz = (uint32_t)((lr >> 2) & 1) << 4;
        bB[nj] = pairBase + row * 32 + (csel ^ bswz);
    }

    float acc[2][8][4];                   // 64 accumulator regs
#pragma unroll
    for (int mi = 0; mi < 2; mi++)
#pragma unroll
        for (int nq = 0; nq < 8; nq++)
#pragma unroll
            for (int q = 0; q < 4; q++) acc[mi][nq][q] = 0.f;
    float rs[4] = {0.f, 0.f, 0.f, 0.f};

    int barid = 1 + pair;

    // mainloop: 32 macro-iters (k32 each) = 2 N-chunks x 16. Pair barriers only.
    for (int i = 0; i < 32; i++) {
        BAR_SYNC(barid, 64);              // both warps done iter i-1:
                                          // group-(i+2) slots free
        if (i + 2 < 32)
            prefetch_grp(g_W1T, i + 2, pairBase, pair, m_part, lane);
        else
            CP_COMMIT();                  // keep group count aligned
        CP_WAIT(2);                       // own group i landed
        BAR_SYNC(barid, 64);              // partner's group i landed

#pragma unroll
        for (int step = 0; step < 2; step++) {
            int c = 2 * i + step;
            uint32_t kb = (uint32_t)(c & 31) * 32;
            uint32_t slotoff = (uint32_t)(c % 6) * 2048;
            uint32_t A[2][4], B[4][4];
#pragma unroll
            for (int mi = 0; mi < 2; mi++)
                ldsm4(A[mi], aRow[mi] + ((kb | a16) ^ aswz));
#pragma unroll
            for (int nj = 0; nj < 4; nj++)
                ldsm4(B[nj], bB[nj] + slotoff);
#pragma unroll
            for (int mi = 0; mi < 2; mi++)
#pragma unroll
                for (int nj = 0; nj < 4; nj++) {
                    mma_f16(acc[mi][nj * 2],     A[mi], B[nj][0], B[nj][1]);
                    mma_f16(acc[mi][nj * 2 + 1], A[mi], B[nj][2], B[nj][3]);
                }
        }

        if ((i & 15) == 15) {
            // fold this 256-wide N chunk into per-row score partials
            int nc = i >> 4;
            int t2 = (lane & 3) * 2;
#pragma unroll
            for (int mi = 0; mi < 2; mi++)
#pragma unroll
                for (int nq = 0; nq < 8; nq++) {
                    int n0 = nc * 256 + pair * 64 + nq * 8 + t2;
                    float2 bb = __ldg((const float2*)(pb1 + n0));
                    float2 ww = __ldg((const float2*)(pw2 + n0));
                    float* cc = acc[mi][nq];
                    rs[mi * 2 + 0] += fmaxf(cc[0] + bb.x, 0.f) * ww.x +
                                      fmaxf(cc[1] + bb.y, 0.f) * ww.y;
                    rs[mi * 2 + 1] += fmaxf(cc[2] + bb.x, 0.f) * ww.x +
                                      fmaxf(cc[3] + bb.y, 0.f) * ww.y;
                    cc[0] = cc[1] = cc[2] = cc[3] = 0.f;
                }
        }
    }

    // ring is dead now; overlay sc/wts on it
    __syncthreads();
    float* sc = (float*)(smem + OFF_SC);
    if (tid < 64) sc[tid] = 0.f;
    __syncthreads();

    // reduce the 4 lanes sharing each row, combine the 4 pair warps
#pragma unroll
    for (int i = 0; i < 4; i++) {
        rs[i] += __shfl_xor_sync(0xffffffffu, rs[i], 1);
        rs[i] += __shfl_xor_sync(0xffffffffu, rs[i], 2);
    }
    if ((lane & 3) == 0) {
        int g = lane >> 2;
#pragma unroll
        for (int mi = 0; mi < 2; mi++) {
            atomicAdd(&sc[m_part * 32 + mi * 16 + g],     rs[mi * 2 + 0]);
            atomicAdd(&sc[m_part * 32 + mi * 16 + 8 + g], rs[mi * 2 + 1]);
        }
    }
    __syncthreads();

    // masked softmax over this path's 64 positions
    if (tid < 64) {
        int len = lengths[blockIdx.x];
        float mx = -1e30f;
        for (int j = 0; j < 64; j++) if (j < len) mx = fmaxf(mx, sc[j]);
        float sum = 0.f;
        for (int j = 0; j < 64; j++) if (j < len) sum += expf(sc[j] - mx);
        float w = (tid < len) ? expf(sc[tid] - mx) / sum : 0.f;
        ((float*)(smem + OFF_WTS))[tid] = w;
    }
    __syncthreads();

    // weighted sum of X rows (fp16, swizzled) -> paths_fea
    const float* wts = (const float*)(smem + OFF_WTS);
    {
        int dp = tid;                     // fp16x2 column (0..255)
        float a0 = 0.f, a1 = 0.f;
        uint32_t cbyte = (uint32_t)dp * 4;
#pragma unroll 8
        for (int l = 0; l < 64; l++) {
            uint32_t off = OFF_XS + l * 1024 +
                           (cbyte ^ (((uint32_t)(l & 7)) << 4));
            uint32_t v = *(const uint32_t*)(smem + off);
            __half2 hv = *(__half2*)&v;
            float wl = wts[l];
            a0 = fmaf(wl, __half2float(hv.x), a0);
            a1 = fmaf(wl, __half2float(hv.y), a1);
        }
        float* dst = g_pf + (size_t)blockIdx.x * 512 + dp * 2;
        dst[0] = a0;
        dst[1] = a1;
    }
}

// ============================================================================
//          k_agg (R11: grid 128 = 64 row-blocks x 2 N-halves)
// ============================================================================

__device__ __forceinline__ void ag_prefetch(const __half* __restrict__ Wt,
                                            int s, int buf, uint32_t sb) {
    int tid = threadIdx.x;
    const __half* src = Wt + s * 64;      // chunk s: rows [0,256), k [s*64,+64)
#pragma unroll
    for (int i = 0; i < 8; i++) {
        int idx = tid + i * 256;
        int nl = idx >> 3;
        int q  = idx & 7;
        uint32_t dst = sb + OFFWS_AGG + buf * 36864 + nl * AG_WSTR + q * 16;
        CP_ASYNC16(dst, src + (size_t)nl * 512 + q * 8);
    }
    CP_COMMIT();
}

__global__ void __launch_bounds__(256, 1)
k_agg(const float* __restrict__ ab1, const float* __restrict__ aw2,
      const float* __restrict__ ab2) {
    extern __shared__ char smem[];
    uint32_t sb = smem_u32(smem);
    int tid = threadIdx.x;
    int lane = tid & 31, wid = tid >> 5;
    int n_part = wid;                     // 32-col slice of this 256-N-half
    int rb = blockIdx.x >> 1;             // row block (64 paths)
    int h  = blockIdx.x & 1;              // N half
    const __half* Wt = g_aW1T + (size_t)h * 256 * 512;

    ag_prefetch(Wt, 0, 0, sb);
    ag_prefetch(Wt, 1, 1, sb);
    ag_prefetch(Wt, 2, 2, sb);

    float* b1s = (float*)(smem + AG_B1);
    float* w2s = (float*)(smem + AG_W2);
    float* sc  = (float*)(smem + AG_SC);
    for (int i = tid; i < 512; i += 256) { b1s[i] = ab1[i]; w2s[i] = aw2[i]; }
    if (tid < 64) sc[tid] = 0.f;

    const float* X = g_pf + (size_t)rb * 64 * 512;
#pragma unroll 4
    for (int i = 0; i < 32; i++) {
        int idx = tid + i * 256;
        int m = idx >> 7;
        int q = idx & 127;
        float4 v = *(const float4*)(X + (size_t)m * 512 + q * 4);
        sts_f16x4(smem, AG_XS + m * AG_XSTR + q * 8, v);
    }

    int lr = lane & 7;
    uint32_t aA[4];
#pragma unroll
    for (int mi = 0; mi < 4; mi++)
        aA[mi] = sb + AG_XS +
                 (mi * 16 + ((lane >> 3) & 1) * 8 + lr) * AG_XSTR +
                 (lane >> 4) * 16;
    uint32_t bA[2];
#pragma unroll
    for (int nj = 0; nj < 2; nj++)
        bA[nj] = sb + OFFWS_AGG +
                 (n_part * 32 + nj * 16 + (lane >> 4) * 8 + lr) * AG_WSTR +
                 ((lane >> 3) & 1) * 16;

    float acc[4][4][4];
#pragma unroll
    for (int mi = 0; mi < 4; mi++)
#pragma unroll
        for (int nq = 0; nq < 4; nq++)
#pragma unroll
            for (int q = 0; q < 4; q++) acc[mi][nq][q] = 0.f;
    float rs[8];
#pragma unroll
    for (int i = 0; i < 8; i++) rs[i] = 0.f;

    for (int s = 0; s < 8; s++) {         // 8 k-chunks (k64 each), 1 N-half
        __syncthreads();
        if (s + 3 < 8) ag_prefetch(Wt, s + 3, (s + 3) & 3, sb);
        else CP_COMMIT();
        CP_WAIT(3);
        __syncthreads();

        uint32_t buf = (uint32_t)(s & 3) * 36864;
#pragma unroll
        for (int k16 = 0; k16 < 4; k16++) {
            uint32_t kxX = s * 128 + k16 * 32;
            uint32_t kxW = k16 * 32;
            uint32_t A[4][4], B[2][4];
#pragma unroll
            for (int mi = 0; mi < 4; mi++) ldsm4(A[mi], aA[mi] + kxX);
#pragma unroll
            for (int nj = 0; nj < 2; nj++) ldsm4(B[nj], bA[nj] + buf + kxW);
#pragma unroll
            for (int mi = 0; mi < 4; mi++)
#pragma unroll
                for (int nj = 0; nj < 2; nj++) {
                    mma_f16(acc[mi][nj * 2],     A[mi], B[nj][0], B[nj][1]);
                    mma_f16(acc[mi][nj * 2 + 1], A[mi], B[nj][2], B[nj][3]);
                }
        }
    }

    // fold the 256-wide N half
    {
        int t2 = (lane & 3) * 2;
#pragma unroll
        for (int mi = 0; mi < 4; mi++)
#pragma unroll
            for (int nq = 0; nq < 4; nq++) {
                int n0 = h * 256 + n_part * 32 + nq * 8 + t2;
                float bb0 = b1s[n0], bb1 = b1s[n0 + 1];
                float ww0 = w2s[n0], ww1 = w2s[n0 + 1];
                float* cc = acc[mi][nq];
                rs[mi * 2 + 0] += fmaxf(cc[0] + bb0, 0.f) * ww0 +
                                  fmaxf(cc[1] + bb1, 0.f) * ww1;
                rs[mi * 2 + 1] += fmaxf(cc[2] + bb0, 0.f) * ww0 +
                                  fmaxf(cc[3] + bb1, 0.f) * ww1;
            }
    }

#pragma unroll
    for (int i = 0; i < 8; i++) {
        rs[i] += __shfl_xor_sync(0xffffffffu, rs[i], 1);
        rs[i] += __shfl_xor_sync(0xffffffffu, rs[i], 2);
    }
    if ((lane & 3) == 0) {
        int g = lane >> 2;
#pragma unroll
        for (int mi = 0; mi < 4; mi++) {
            atomicAdd(&sc[mi * 16 + g],     rs[mi * 2 + 0]);
            atomicAdd(&sc[mi * 16 + 8 + g], rs[mi * 2 + 1]);
        }
    }
    __syncthreads();

    // accumulate partial logits (g_a pre-zeroed by k_zero)
    if (tid < 64)
        atomicAdd(&g_a[rb * 64 + tid], sc[tid] + (h == 0 ? ab2[0] : 0.f));
}

// ---------------- kernel 0: transpose + convert weights ----------------------
__global__ void k_conv(const float* __restrict__ src, __half* __restrict__ dst) {
    __shared__ float tile[64][65];
    int k0 = blockIdx.y * 64, n0 = blockIdx.x * 64;
    for (int i = threadIdx.x; i < 4096; i += 256) {
        int r = i >> 6, cth = i & 63;
        tile[r][cth] = src[(size_t)(k0 + r) * 512 + n0 + cth];
    }
    __syncthreads();
    for (int i = threadIdx.x; i < 4096; i += 256) {
        int r = i >> 6, cth = i & 63;
        dst[(size_t)(n0 + r) * 512 + k0 + cth] = __float2half_rn(tile[cth][r]);
    }
}

// ---------------- kernel 0b: zero g_a (also keeps k_path at ncu slot) ---------
__global__ void k_zero() {
    g_a[blockIdx.x * 64 + threadIdx.x] = 0.f;   // k_agg accumulates into this
}

// ---------------- kernel 3: softmax over 4096 paths ---------------------------
__global__ void k_soft() {
    __shared__ float red[1024];
    int t = threadIdx.x;
    float m = -1e30f;
    for (int i = t; i < NPATHS; i += 1024) m = fmaxf(m, g_a[i]);
    red[t] = m;
    __syncthreads();
    for (int s = 512; s > 0; s >>= 1) {
        if (t < s) red[t] = fmaxf(red[t], red[t + s]);
        __syncthreads();
    }
    float M = red[0];
    __syncthreads();
    float sum = 0.f;
    for (int i = t; i < NPATHS; i += 1024) sum += expf(g_a[i] - M);
    red[t] = sum;
    __syncthreads();
    for (int s = 512; s > 0; s >>= 1) {
        if (t < s) red[t] += red[t + s];
        __syncthreads();
    }
    float S = red[0];
    for (int i = t; i < NPATHS; i += 1024) g_aw[i] = expf(g_a[i] - M) / S;
}

// ---------------- kernel 4: partial weighted sums -----------------------------
__global__ void k_red() {
    int b = blockIdx.x, t = threadIdx.x;
    float a0 = 0.f, a1 = 0.f;
    for (int p = 0; p < 64; p++) {
        int pg = b * 64 + p;
        float w = g_aw[pg];
        const float* row = g_pf + (size_t)pg * 512;
        a0 = fmaf(w, row[t], a0);
        a1 = fmaf(w, row[t + 256], a1);
    }
    g_part[(size_t)b * 512 + t] = a0;
    g_part[(size_t)b * 512 + t + 256] = a1;
}

// ---------------- kernel 5: final reduction -----------------------------------
__global__ void k_fin(float* __restrict__ out) {
    int t = threadIdx.x;
    float s = 0.f;
    for (int b = 0; b < 64; b++) s += g_part[(size_t)b * 512 + t];
    out[t] = s;
}

// ---------------- entry -------------------------------------------------------
extern "C" void kernel_launch(void* const* d_in, const int* in_sizes, int n_in,
                              void* d_out, int out_size) {
    const float* nodes   = (const float*)d_in[0];
    const int*   lengths = (const int*)  d_in[1];
    const float* pW1     = (const float*)d_in[2];
    const float* pb1     = (const float*)d_in[3];
    const float* pw2     = (const float*)d_in[4];
    const float* pb2     = (const float*)d_in[5];
    const float* aW1     = (const float*)d_in[6];
    const float* ab1     = (const float*)d_in[7];
    const float* aw2     = (const float*)d_in[8];
    const float* ab2     = (const float*)d_in[9];
    float* out = (float*)d_out;
    (void)pb2;

    cudaFuncSetAttribute(k_path, cudaFuncAttributeMaxDynamicSharedMemorySize, SMEM_PATH);
    cudaFuncSetAttribute(k_agg,  cudaFuncAttributeMaxDynamicSharedMemorySize, SMEM_AGG);

    __half* w1t;  cudaGetSymbolAddress((void**)&w1t,  g_W1T);
    __half* aw1t; cudaGetSymbolAddress((void**)&aw1t, g_aW1T);

    k_conv<<<dim3(8, 8), 256>>>(pW1, w1t);     // idx 0
    k_conv<<<dim3(8, 8), 256>>>(aW1, aw1t);    // idx 1
    k_zero<<<64, 64>>>();                      // idx 2 (zeroes g_a; ncu slot)
    k_path<<<NPATHS, 256, SMEM_PATH>>>(nodes, lengths, pb1, pw2, pb2);  // idx 3
    k_agg<<<128, 256, SMEM_AGG>>>(ab1, aw2, ab2);                       // idx 4
    k_soft<<<1, 1024>>>();
    k_red<<<64, 256>>>();
    k_fin<<<1, 512>>>(out);
}